// round 10
// baseline (speedup 1.0000x reference)
#include <cuda_runtime.h>
#include <cstdint>

// ---------------- problem constants ----------------
#define N_NODES 50000
#define E_MAX   800000
#define Q_MAX   400000
constexpr int CIN = 256;   // input channels
constexpr int C1  = 128;   // hidden channels
constexpr int C2  = 64;    // output channels

// ---------------- device scratch (static; no allocs allowed) ----------------
__device__ int g_is64;                                  // 1 if index buffers are int64
__device__ __align__(16) int   g_src   [E_MAX];         // sanitized edge src
__device__ __align__(16) int   g_dst   [E_MAX];         // sanitized edge dst
__device__ __align__(16) int   g_qa    [Q_MAX];         // sanitized query endpoint a
__device__ __align__(16) int   g_qb    [Q_MAX];         // sanitized query endpoint b
__device__ __align__(16) int   g_deg   [N_NODES];       // in-degree (real edges only)
__device__ __align__(16) int   g_off   [N_NODES + 1];   // CSR offsets
__device__ __align__(16) int   g_cur   [N_NODES];       // fill cursors
__device__ __align__(16) int   g_srcidx[E_MAX];         // CSR column (src) indices
__device__ __align__(16) float g_dinv  [N_NODES];
__device__ __align__(16) float g_hs1[(size_t)N_NODES * C1];  // dinv * (x @ W1)
__device__ __align__(16) float g_h  [(size_t)N_NODES * C1];  // relu layer-1 output
__device__ __align__(16) float g_hs2[(size_t)N_NODES * C2];  // dinv * (h @ W2)
__device__ __align__(16) float g_z  [(size_t)N_NODES * C2];  // layer-2 output

__device__ __forceinline__ int clamp_idx(long long v) {
    if (v < 0) v = 0;
    if (v >= N_NODES) v = N_NODES - 1;
    return (int)v;
}

// packed fp32x2 FMA (sm_100+): d = a * b + d, elementwise on two packed floats
#define FFMA2(d, a, b) \
    asm("fma.rn.f32x2 %0, %1, %2, %0;" : "+l"(d) : "l"(a), "l"(b))

__device__ __forceinline__ unsigned long long pack_dup(float v) {
    unsigned long long r;
    unsigned u = __float_as_uint(v);
    asm("mov.b64 %0, {%1, %1};" : "=l"(r) : "r"(u));
    return r;
}

// ---------------- dtype detection: int64 buffers have zero high words ----------------
__global__ void detect_kernel(const int* __restrict__ ei32) {
    int lane = threadIdx.x;              // 0..31
    int v = ei32[2 * lane + 1];
    unsigned nz = __ballot_sync(0xffffffffu, v != 0);
    if (lane == 0) g_is64 = (nz == 0u) ? 1 : 0;
}

// ---------------- zero degree ----------------
__global__ void zero_deg_kernel() {
    int i = blockIdx.x * blockDim.x + threadIdx.x;
    if (i < N_NODES) g_deg[i] = 0;
}

// ---------------- normalize edges (either dtype) + degree count ----------------
__global__ void convert_edges_kernel(const void* __restrict__ ei, int E) {
    int e = blockIdx.x * blockDim.x + threadIdx.x;
    if (e >= E) return;
    int s, d;
    if (g_is64) {
        const long long* p = (const long long*)ei;
        s = clamp_idx(p[e]);
        d = clamp_idx(p[E + e]);
    } else {
        const int* p = (const int*)ei;
        s = clamp_idx(p[e]);
        d = clamp_idx(p[E + e]);
    }
    g_src[e] = s;
    g_dst[e] = d;
    atomicAdd(&g_deg[d], 1);
}

// ---------------- normalize queries (pos then neg concatenated) ----------------
__global__ void convert_queries_kernel(const void* __restrict__ pos, const void* __restrict__ neg,
                                       int Ep, int En) {
    int i = blockIdx.x * blockDim.x + threadIdx.x;
    if (i >= Ep + En) return;
    int a, b;
    if (g_is64) {
        if (i < Ep) {
            const long long* p = (const long long*)pos;
            a = clamp_idx(p[i]);
            b = clamp_idx(p[Ep + i]);
        } else {
            const long long* p = (const long long*)neg;
            a = clamp_idx(p[i - Ep]);
            b = clamp_idx(p[En + i - Ep]);
        }
    } else {
        if (i < Ep) {
            const int* p = (const int*)pos;
            a = clamp_idx(p[i]);
            b = clamp_idx(p[Ep + i]);
        } else {
            const int* p = (const int*)neg;
            a = clamp_idx(p[i - Ep]);
            b = clamp_idx(p[En + i - Ep]);
        }
    }
    g_qa[i] = a;
    g_qb[i] = b;
}

__global__ void dinv_kernel() {
    int n = blockIdx.x * blockDim.x + threadIdx.x;
    if (n < N_NODES) g_dinv[n] = rsqrtf((float)(g_deg[n] + 1));  // +1 self-loop
}

// ---------------- exclusive scan of g_deg -> g_off / g_cur (single block, 1024 threads) ----------------
__global__ void __launch_bounds__(1024) scan_kernel() {
    __shared__ int wsum[32];
    __shared__ int s_carry;
    const int tid  = threadIdx.x;
    const int lane = tid & 31;
    const int wid  = tid >> 5;
    if (tid == 0) s_carry = 0;
    __syncthreads();

    for (int base = 0; base < N_NODES; base += 1024) {
        int i = base + tid;
        int v = (i < N_NODES) ? g_deg[i] : 0;
        int inc = v;
#pragma unroll
        for (int o = 1; o < 32; o <<= 1) {
            int t = __shfl_up_sync(0xffffffffu, inc, o);
            if (lane >= o) inc += t;
        }
        if (lane == 31) wsum[wid] = inc;
        __syncthreads();
        if (wid == 0) {
            int w = wsum[lane];
            int winc = w;
#pragma unroll
            for (int o = 1; o < 32; o <<= 1) {
                int t = __shfl_up_sync(0xffffffffu, winc, o);
                if (lane >= o) winc += t;
            }
            wsum[lane] = winc;
        }
        __syncthreads();
        int excl = s_carry + ((wid > 0) ? wsum[wid - 1] : 0) + inc - v;
        if (i < N_NODES) { g_off[i] = excl; g_cur[i] = excl; }
        int chunk_total = wsum[31];
        __syncthreads();
        if (tid == 0) s_carry += chunk_total;
        __syncthreads();
    }
    if (threadIdx.x == 0) g_off[N_NODES] = s_carry;
}

// ---------------- CSR bucket fill (int atomics only) ----------------
__global__ void fill_kernel(int E) {
    int e = blockIdx.x * blockDim.x + threadIdx.x;
    if (e < E) {
        int pos = atomicAdd(&g_cur[g_dst[e]], 1);
        g_srcidx[pos] = g_src[e];
    }
}

// ---------------- tiled SGEMM with packed f32x2 FMA ----------------
// out[m, n] = dinv[m] * sum_k A[m,k] * W[k,n]
// BM=128, BK=16, 256 threads, thread tile TM=8 x TN=(N/16); inner loop uses
// fma.rn.f32x2 (2 FMA/instr) -> 2x fp32 FMA throughput vs scalar FFMA.
template <int N, int K>
__global__ void __launch_bounds__(256)
gemm_scaled(const float* __restrict__ A, const float* __restrict__ W,
            const float* __restrict__ dinv, float* __restrict__ out, int M) {
    constexpr int BM = 128, BK = 16;
    constexpr int TM = 8;
    constexpr int TN  = N / 16;          // 8 for N=128, 4 for N=64
    constexpr int TN2 = TN / 2;          // packed pairs
    __shared__ float As[BK][BM];
    __shared__ float Bs[BK][N];

    const int tid  = threadIdx.x;
    const int row0 = blockIdx.x * BM;
    const int tm   = (tid / 16) * TM;
    const int tn   = (tid % 16) * TN;

    unsigned long long acc2[TM][TN2];
#pragma unroll
    for (int i = 0; i < TM; i++)
#pragma unroll
        for (int j = 0; j < TN2; j++) acc2[i][j] = 0ull;   // pair of +0.0f

    for (int k0 = 0; k0 < K; k0 += BK) {
        // load A tile: BM x BK = 2048 floats = 512 float4, 2 per thread (transposed store)
#pragma unroll
        for (int l = 0; l < 2; l++) {
            int f  = tid + l * 256;
            int r  = f / 4;
            int cs = (f % 4) * 4;
            float4 v = make_float4(0.f, 0.f, 0.f, 0.f);
            int gr = row0 + r;
            if (gr < M) v = *reinterpret_cast<const float4*>(&A[(size_t)gr * K + k0 + cs]);
            As[cs + 0][r] = v.x;
            As[cs + 1][r] = v.y;
            As[cs + 2][r] = v.z;
            As[cs + 3][r] = v.w;
        }
        // load B tile: BK x N floats
        constexpr int BF4 = BK * N / 4;
#pragma unroll
        for (int f = tid; f < BF4; f += 256) {
            int r = f / (N / 4);
            int c = (f % (N / 4)) * 4;
            *reinterpret_cast<float4*>(&Bs[r][c]) =
                *reinterpret_cast<const float4*>(&W[(size_t)(k0 + r) * N + c]);
        }
        __syncthreads();

#pragma unroll
        for (int kk = 0; kk < BK; kk++) {
            float a[TM];
#pragma unroll
            for (int i = 0; i < TM; i += 4)
                *reinterpret_cast<float4*>(&a[i]) = *reinterpret_cast<float4*>(&As[kk][tm + i]);
            unsigned long long ad[TM];
#pragma unroll
            for (int i = 0; i < TM; i++) ad[i] = pack_dup(a[i]);

            unsigned long long b2[TN2];
#pragma unroll
            for (int j = 0; j < TN2; j += 2) {
                ulonglong2 u = *reinterpret_cast<ulonglong2*>(&Bs[kk][tn + 2 * j]);
                b2[j]     = u.x;
                b2[j + 1] = u.y;
            }
#pragma unroll
            for (int i = 0; i < TM; i++)
#pragma unroll
                for (int j = 0; j < TN2; j++)
                    FFMA2(acc2[i][j], ad[i], b2[j]);
        }
        __syncthreads();
    }

    // epilogue: unpack, scale by dinv[row], store
#pragma unroll
    for (int i = 0; i < TM; i++) {
        int gr = row0 + tm + i;
        if (gr >= M) continue;
        float s = dinv[gr];
#pragma unroll
        for (int j = 0; j < TN2; j += 2) {
            unsigned lo0, hi0, lo1, hi1;
            asm("mov.b64 {%0, %1}, %2;" : "=r"(lo0), "=r"(hi0) : "l"(acc2[i][j]));
            asm("mov.b64 {%0, %1}, %2;" : "=r"(lo1), "=r"(hi1) : "l"(acc2[i][j + 1]));
            float4 v;
            v.x = __uint_as_float(lo0) * s;
            v.y = __uint_as_float(hi0) * s;
            v.z = __uint_as_float(lo1) * s;
            v.w = __uint_as_float(hi1) * s;
            *reinterpret_cast<float4*>(&out[(size_t)gr * N + tn + 2 * j]) = v;
        }
    }
}

// ---------------- gather + combine, C=128: one warp per node, float4 per lane ----------------
template <bool RELU>
__global__ void gather128_kernel(const float* __restrict__ hs, float* __restrict__ out,
                                 const float* __restrict__ bias) {
    int gw   = (blockIdx.x * blockDim.x + threadIdx.x) >> 5;
    int lane = threadIdx.x & 31;
    if (gw >= N_NODES) return;
    const int s = g_off[gw];
    const int e = g_off[gw + 1];

    // self-loop contribution
    float4 acc = *reinterpret_cast<const float4*>(&hs[(size_t)gw * C1 + lane * 4]);

    int k = s;
    for (; k + 4 <= e; k += 4) {
        int s0 = g_srcidx[k + 0];
        int s1 = g_srcidx[k + 1];
        int s2 = g_srcidx[k + 2];
        int s3 = g_srcidx[k + 3];
        float4 v0 = *reinterpret_cast<const float4*>(&hs[(size_t)s0 * C1 + lane * 4]);
        float4 v1 = *reinterpret_cast<const float4*>(&hs[(size_t)s1 * C1 + lane * 4]);
        float4 v2 = *reinterpret_cast<const float4*>(&hs[(size_t)s2 * C1 + lane * 4]);
        float4 v3 = *reinterpret_cast<const float4*>(&hs[(size_t)s3 * C1 + lane * 4]);
        acc.x += v0.x + v1.x + v2.x + v3.x;
        acc.y += v0.y + v1.y + v2.y + v3.y;
        acc.z += v0.z + v1.z + v2.z + v3.z;
        acc.w += v0.w + v1.w + v2.w + v3.w;
    }
    for (; k < e; k++) {
        int sk = g_srcidx[k];
        float4 v = *reinterpret_cast<const float4*>(&hs[(size_t)sk * C1 + lane * 4]);
        acc.x += v.x; acc.y += v.y; acc.z += v.z; acc.w += v.w;
    }

    float  d = g_dinv[gw];
    float4 b = *reinterpret_cast<const float4*>(&bias[lane * 4]);
    float4 o;
    o.x = d * acc.x + b.x;
    o.y = d * acc.y + b.y;
    o.z = d * acc.z + b.z;
    o.w = d * acc.w + b.w;
    if (RELU) {
        o.x = fmaxf(o.x, 0.f); o.y = fmaxf(o.y, 0.f);
        o.z = fmaxf(o.z, 0.f); o.w = fmaxf(o.w, 0.f);
    }
    *reinterpret_cast<float4*>(&out[(size_t)gw * C1 + lane * 4]) = o;
}

// ---------------- gather + combine, C=64: one warp per node, float2 per lane ----------------
template <bool RELU>
__global__ void gather64_kernel(const float* __restrict__ hs, float* __restrict__ out,
                                const float* __restrict__ bias) {
    int gw   = (blockIdx.x * blockDim.x + threadIdx.x) >> 5;
    int lane = threadIdx.x & 31;
    if (gw >= N_NODES) return;
    const int s = g_off[gw];
    const int e = g_off[gw + 1];

    float2 acc = *reinterpret_cast<const float2*>(&hs[(size_t)gw * C2 + lane * 2]);

    int k = s;
    for (; k + 4 <= e; k += 4) {
        int s0 = g_srcidx[k + 0];
        int s1 = g_srcidx[k + 1];
        int s2 = g_srcidx[k + 2];
        int s3 = g_srcidx[k + 3];
        float2 v0 = *reinterpret_cast<const float2*>(&hs[(size_t)s0 * C2 + lane * 2]);
        float2 v1 = *reinterpret_cast<const float2*>(&hs[(size_t)s1 * C2 + lane * 2]);
        float2 v2 = *reinterpret_cast<const float2*>(&hs[(size_t)s2 * C2 + lane * 2]);
        float2 v3 = *reinterpret_cast<const float2*>(&hs[(size_t)s3 * C2 + lane * 2]);
        acc.x += v0.x + v1.x + v2.x + v3.x;
        acc.y += v0.y + v1.y + v2.y + v3.y;
    }
    for (; k < e; k++) {
        int sk = g_srcidx[k];
        float2 v = *reinterpret_cast<const float2*>(&hs[(size_t)sk * C2 + lane * 2]);
        acc.x += v.x; acc.y += v.y;
    }

    float  d = g_dinv[gw];
    float2 b = *reinterpret_cast<const float2*>(&bias[lane * 2]);
    float2 o;
    o.x = d * acc.x + b.x;
    o.y = d * acc.y + b.y;
    if (RELU) { o.x = fmaxf(o.x, 0.f); o.y = fmaxf(o.y, 0.f); }
    *reinterpret_cast<float2*>(&out[(size_t)gw * C2 + lane * 2]) = o;
}

// ---------------- logits: out[e] = dot(z[qa], z[qb]) over C2=64 dims ----------------
__global__ void logits_kernel(int Q, const float* __restrict__ z, float* __restrict__ out) {
    long long idx = (long long)blockIdx.x * blockDim.x + threadIdx.x;
    long long e = idx / 16;
    int j       = (int)(idx % 16);
    if (e >= Q) return;
    int a = g_qa[e];
    int b = g_qb[e];
    float4 va = *reinterpret_cast<const float4*>(&z[(size_t)a * C2 + j * 4]);
    float4 vb = *reinterpret_cast<const float4*>(&z[(size_t)b * C2 + j * 4]);
    float d = va.x * vb.x + va.y * vb.y + va.z * vb.z + va.w * vb.w;
#pragma unroll
    for (int off = 8; off > 0; off >>= 1)
        d += __shfl_xor_sync(0xffffffffu, d, off, 16);
    if (j == 0) out[e] = d;
}

// ---------------- launch ----------------
extern "C" void kernel_launch(void* const* d_in, const int* in_sizes, int n_in,
                              void* d_out, int out_size) {
    const float* x   = (const float*)d_in[0];
    const void*  ei  = d_in[1];
    const void*  pos = d_in[2];
    const void*  neg = d_in[3];
    const float* W1  = (const float*)d_in[4];
    const float* b1  = (const float*)d_in[5];
    const float* W2  = (const float*)d_in[6];
    const float* b2  = (const float*)d_in[7];
    float* out = (float*)d_out;

    const int E  = in_sizes[1] / 2;   // 800000
    const int Ep = in_sizes[2] / 2;   // 200000
    const int En = in_sizes[3] / 2;   // 200000
    const int Q  = Ep + En;
    const int M  = N_NODES;

    float *hs1, *h, *hs2, *z, *dinv;
    cudaGetSymbolAddress((void**)&hs1,  g_hs1);
    cudaGetSymbolAddress((void**)&h,    g_h);
    cudaGetSymbolAddress((void**)&hs2,  g_hs2);
    cudaGetSymbolAddress((void**)&z,    g_z);
    cudaGetSymbolAddress((void**)&dinv, g_dinv);

    // ---- dtype detect + normalize indices + CSR build ----
    detect_kernel<<<1, 32>>>((const int*)ei);
    zero_deg_kernel<<<(N_NODES + 255) / 256, 256>>>();
    convert_edges_kernel<<<(E + 255) / 256, 256>>>(ei, E);
    convert_queries_kernel<<<(Q + 255) / 256, 256>>>(pos, neg, Ep, En);
    dinv_kernel<<<(N_NODES + 255) / 256, 256>>>();
    scan_kernel<<<1, 1024>>>();
    fill_kernel<<<(E + 255) / 256, 256>>>(E);

    // ---- layer 1 ----
    gemm_scaled<C1, CIN><<<(M + 127) / 128, 256>>>(x, W1, dinv, hs1, M);
    gather128_kernel<true><<<(N_NODES * 32 + 255) / 256, 256>>>(hs1, h, b1);

    // ---- layer 2 ----
    gemm_scaled<C2, C1><<<(M + 127) / 128, 256>>>(h, W2, dinv, hs2, M);
    gather64_kernel<false><<<(N_NODES * 32 + 255) / 256, 256>>>(hs2, z, b2);

    // ---- logits ----
    {
        long long tot = (long long)Q * 16;
        int blocks = (int)((tot + 255) / 256);
        logits_kernel<<<blocks, 256>>>(Q, z, out);
    }
}

// round 11
// speedup vs baseline: 1.4471x; 1.4471x over previous
#include <cuda_runtime.h>
#include <cstdint>

// ---------------- problem constants ----------------
#define N_NODES 50000
#define E_MAX   800000
#define Q_MAX   400000
constexpr int CIN = 256;   // input channels
constexpr int C1  = 128;   // hidden channels
constexpr int C2  = 64;    // output channels

// ---------------- device scratch (static; no allocs allowed) ----------------
__device__ int g_is64;                                  // 1 if index buffers are int64
__device__ __align__(16) int   g_src   [E_MAX];         // sanitized edge src
__device__ __align__(16) int   g_dst   [E_MAX];         // sanitized edge dst
__device__ __align__(16) int   g_qa    [Q_MAX];         // sanitized query endpoint a
__device__ __align__(16) int   g_qb    [Q_MAX];         // sanitized query endpoint b
__device__ __align__(16) int   g_deg   [N_NODES];       // in-degree (real edges only)
__device__ __align__(16) int   g_off   [N_NODES + 1];   // CSR offsets
__device__ __align__(16) int   g_cur   [N_NODES];       // fill cursors
__device__ __align__(16) int   g_srcidx[E_MAX];         // CSR column (src) indices
__device__ __align__(16) float g_dinv  [N_NODES];
__device__ __align__(16) float g_hs1[(size_t)N_NODES * C1];  // x @ W1 (unscaled)
__device__ __align__(16) float g_h  [(size_t)N_NODES * C1];  // relu layer-1 output
__device__ __align__(16) float g_hs2[(size_t)N_NODES * C2];  // h @ W2 (unscaled)
__device__ __align__(16) float g_z  [(size_t)N_NODES * C2];  // layer-2 output

__device__ __forceinline__ int clamp_idx(long long v) {
    if (v < 0) v = 0;
    if (v >= N_NODES) v = N_NODES - 1;
    return (int)v;
}

// ---------------- dtype detection: int64 buffers have zero high words ----------------
__global__ void detect_kernel(const int* __restrict__ ei32) {
    int lane = threadIdx.x;              // 0..31
    int v = ei32[2 * lane + 1];
    unsigned nz = __ballot_sync(0xffffffffu, v != 0);
    if (lane == 0) g_is64 = (nz == 0u) ? 1 : 0;
}

// ---------------- zero degree ----------------
__global__ void zero_deg_kernel() {
    int i = blockIdx.x * blockDim.x + threadIdx.x;
    if (i < N_NODES) g_deg[i] = 0;
}

// ---------------- normalize edges (either dtype) + degree count ----------------
__global__ void convert_edges_kernel(const void* __restrict__ ei, int E) {
    int e = blockIdx.x * blockDim.x + threadIdx.x;
    if (e >= E) return;
    int s, d;
    if (g_is64) {
        const long long* p = (const long long*)ei;
        s = clamp_idx(p[e]);
        d = clamp_idx(p[E + e]);
    } else {
        const int* p = (const int*)ei;
        s = clamp_idx(p[e]);
        d = clamp_idx(p[E + e]);
    }
    g_src[e] = s;
    g_dst[e] = d;
    atomicAdd(&g_deg[d], 1);
}

// ---------------- normalize queries (pos then neg concatenated) ----------------
__global__ void convert_queries_kernel(const void* __restrict__ pos, const void* __restrict__ neg,
                                       int Ep, int En) {
    int i = blockIdx.x * blockDim.x + threadIdx.x;
    if (i >= Ep + En) return;
    int a, b;
    if (g_is64) {
        if (i < Ep) {
            const long long* p = (const long long*)pos;
            a = clamp_idx(p[i]);
            b = clamp_idx(p[Ep + i]);
        } else {
            const long long* p = (const long long*)neg;
            a = clamp_idx(p[i - Ep]);
            b = clamp_idx(p[En + i - Ep]);
        }
    } else {
        if (i < Ep) {
            const int* p = (const int*)pos;
            a = clamp_idx(p[i]);
            b = clamp_idx(p[Ep + i]);
        } else {
            const int* p = (const int*)neg;
            a = clamp_idx(p[i - Ep]);
            b = clamp_idx(p[En + i - Ep]);
        }
    }
    g_qa[i] = a;
    g_qb[i] = b;
}

__global__ void dinv_kernel() {
    int n = blockIdx.x * blockDim.x + threadIdx.x;
    if (n < N_NODES) g_dinv[n] = rsqrtf((float)(g_deg[n] + 1));  // +1 self-loop
}

// ---------------- exclusive scan of g_deg -> g_off / g_cur (single block, 1024 threads) ----------------
__global__ void __launch_bounds__(1024) scan_kernel() {
    __shared__ int wsum[32];
    __shared__ int s_carry;
    const int tid  = threadIdx.x;
    const int lane = tid & 31;
    const int wid  = tid >> 5;
    if (tid == 0) s_carry = 0;
    __syncthreads();

    for (int base = 0; base < N_NODES; base += 1024) {
        int i = base + tid;
        int v = (i < N_NODES) ? g_deg[i] : 0;
        int inc = v;
#pragma unroll
        for (int o = 1; o < 32; o <<= 1) {
            int t = __shfl_up_sync(0xffffffffu, inc, o);
            if (lane >= o) inc += t;
        }
        if (lane == 31) wsum[wid] = inc;
        __syncthreads();
        if (wid == 0) {
            int w = wsum[lane];
            int winc = w;
#pragma unroll
            for (int o = 1; o < 32; o <<= 1) {
                int t = __shfl_up_sync(0xffffffffu, winc, o);
                if (lane >= o) winc += t;
            }
            wsum[lane] = winc;
        }
        __syncthreads();
        int excl = s_carry + ((wid > 0) ? wsum[wid - 1] : 0) + inc - v;
        if (i < N_NODES) { g_off[i] = excl; g_cur[i] = excl; }
        int chunk_total = wsum[31];
        __syncthreads();
        if (tid == 0) s_carry += chunk_total;
        __syncthreads();
    }
    if (threadIdx.x == 0) g_off[N_NODES] = s_carry;
}

// ---------------- CSR bucket fill (int atomics only) ----------------
__global__ void fill_kernel(int E) {
    int e = blockIdx.x * blockDim.x + threadIdx.x;
    if (e < E) {
        int pos = atomicAdd(&g_cur[g_dst[e]], 1);
        g_srcidx[pos] = g_src[e];
    }
}

// ---------------- tiled SGEMM: out = A @ W (unscaled) ----------------
// BM=128, BK=16, 256 threads, thread tile TM=8 x TN=(N/16). Scalar FFMA (R9-proven).
template <int N, int K>
__global__ void __launch_bounds__(256)
gemm_kernel(const float* __restrict__ A, const float* __restrict__ W,
            float* __restrict__ out, int M) {
    constexpr int BM = 128, BK = 16;
    constexpr int TM = 8;
    constexpr int TN = N / 16;           // 8 for N=128, 4 for N=64
    __shared__ float As[BK][BM];
    __shared__ float Bs[BK][N];

    const int tid  = threadIdx.x;
    const int row0 = blockIdx.x * BM;
    const int tm   = (tid / 16) * TM;
    const int tn   = (tid % 16) * TN;

    float acc[TM][TN];
#pragma unroll
    for (int i = 0; i < TM; i++)
#pragma unroll
        for (int j = 0; j < TN; j++) acc[i][j] = 0.f;

    for (int k0 = 0; k0 < K; k0 += BK) {
#pragma unroll
        for (int l = 0; l < 2; l++) {
            int f  = tid + l * 256;
            int r  = f / 4;
            int cs = (f % 4) * 4;
            float4 v = make_float4(0.f, 0.f, 0.f, 0.f);
            int gr = row0 + r;
            if (gr < M) v = *reinterpret_cast<const float4*>(&A[(size_t)gr * K + k0 + cs]);
            As[cs + 0][r] = v.x;
            As[cs + 1][r] = v.y;
            As[cs + 2][r] = v.z;
            As[cs + 3][r] = v.w;
        }
        constexpr int BF4 = BK * N / 4;
#pragma unroll
        for (int f = tid; f < BF4; f += 256) {
            int r = f / (N / 4);
            int c = (f % (N / 4)) * 4;
            *reinterpret_cast<float4*>(&Bs[r][c]) =
                *reinterpret_cast<const float4*>(&W[(size_t)(k0 + r) * N + c]);
        }
        __syncthreads();

#pragma unroll
        for (int kk = 0; kk < BK; kk++) {
            float a[TM], b[TN];
#pragma unroll
            for (int i = 0; i < TM; i += 4)
                *reinterpret_cast<float4*>(&a[i]) = *reinterpret_cast<float4*>(&As[kk][tm + i]);
#pragma unroll
            for (int j = 0; j < TN; j += 4)
                *reinterpret_cast<float4*>(&b[j]) = *reinterpret_cast<float4*>(&Bs[kk][tn + j]);
#pragma unroll
            for (int i = 0; i < TM; i++)
#pragma unroll
                for (int j = 0; j < TN; j++) acc[i][j] += a[i] * b[j];
        }
        __syncthreads();
    }

#pragma unroll
    for (int i = 0; i < TM; i++) {
        int gr = row0 + tm + i;
        if (gr >= M) continue;
#pragma unroll
        for (int j = 0; j < TN; j += 4) {
            float4 v;
            v.x = acc[i][j + 0];
            v.y = acc[i][j + 1];
            v.z = acc[i][j + 2];
            v.w = acc[i][j + 3];
            *reinterpret_cast<float4*>(&out[(size_t)gr * N + tn + j]) = v;
        }
    }
}

// ---------------- gather + combine, C=128: one warp per node ----------------
// out[gw] = (relu?)( dinv[gw] * ( hs[gw]*dinv[gw] + sum_src hs[src]*dinv[src] ) + b )
template <bool RELU>
__global__ void gather128_kernel(const float* __restrict__ hs, float* __restrict__ out,
                                 const float* __restrict__ bias) {
    int gw   = (blockIdx.x * blockDim.x + threadIdx.x) >> 5;
    int lane = threadIdx.x & 31;
    if (gw >= N_NODES) return;
    const int s = g_off[gw];
    const int e = g_off[gw + 1];
    const float dself = g_dinv[gw];

    // self-loop contribution
    float4 self = *reinterpret_cast<const float4*>(&hs[(size_t)gw * C1 + lane * 4]);
    float4 acc;
    acc.x = self.x * dself;
    acc.y = self.y * dself;
    acc.z = self.z * dself;
    acc.w = self.w * dself;

    int k = s;
    for (; k + 4 <= e; k += 4) {
        int s0 = g_srcidx[k + 0];
        int s1 = g_srcidx[k + 1];
        int s2 = g_srcidx[k + 2];
        int s3 = g_srcidx[k + 3];
        float d0 = g_dinv[s0], d1 = g_dinv[s1], d2 = g_dinv[s2], d3 = g_dinv[s3];
        float4 v0 = *reinterpret_cast<const float4*>(&hs[(size_t)s0 * C1 + lane * 4]);
        float4 v1 = *reinterpret_cast<const float4*>(&hs[(size_t)s1 * C1 + lane * 4]);
        float4 v2 = *reinterpret_cast<const float4*>(&hs[(size_t)s2 * C1 + lane * 4]);
        float4 v3 = *reinterpret_cast<const float4*>(&hs[(size_t)s3 * C1 + lane * 4]);
        acc.x += v0.x * d0 + v1.x * d1 + v2.x * d2 + v3.x * d3;
        acc.y += v0.y * d0 + v1.y * d1 + v2.y * d2 + v3.y * d3;
        acc.z += v0.z * d0 + v1.z * d1 + v2.z * d2 + v3.z * d3;
        acc.w += v0.w * d0 + v1.w * d1 + v2.w * d2 + v3.w * d3;
    }
    for (; k < e; k++) {
        int sk = g_srcidx[k];
        float dk = g_dinv[sk];
        float4 v = *reinterpret_cast<const float4*>(&hs[(size_t)sk * C1 + lane * 4]);
        acc.x += v.x * dk; acc.y += v.y * dk; acc.z += v.z * dk; acc.w += v.w * dk;
    }

    float4 b = *reinterpret_cast<const float4*>(&bias[lane * 4]);
    float4 o;
    o.x = dself * acc.x + b.x;
    o.y = dself * acc.y + b.y;
    o.z = dself * acc.z + b.z;
    o.w = dself * acc.w + b.w;
    if (RELU) {
        o.x = fmaxf(o.x, 0.f); o.y = fmaxf(o.y, 0.f);
        o.z = fmaxf(o.z, 0.f); o.w = fmaxf(o.w, 0.f);
    }
    *reinterpret_cast<float4*>(&out[(size_t)gw * C1 + lane * 4]) = o;
}

// ---------------- gather + combine, C=64: one warp per node, float2 per lane ----------------
template <bool RELU>
__global__ void gather64_kernel(const float* __restrict__ hs, float* __restrict__ out,
                                const float* __restrict__ bias) {
    int gw   = (blockIdx.x * blockDim.x + threadIdx.x) >> 5;
    int lane = threadIdx.x & 31;
    if (gw >= N_NODES) return;
    const int s = g_off[gw];
    const int e = g_off[gw + 1];
    const float dself = g_dinv[gw];

    float2 self = *reinterpret_cast<const float2*>(&hs[(size_t)gw * C2 + lane * 2]);
    float2 acc;
    acc.x = self.x * dself;
    acc.y = self.y * dself;

    int k = s;
    for (; k + 4 <= e; k += 4) {
        int s0 = g_srcidx[k + 0];
        int s1 = g_srcidx[k + 1];
        int s2 = g_srcidx[k + 2];
        int s3 = g_srcidx[k + 3];
        float d0 = g_dinv[s0], d1 = g_dinv[s1], d2 = g_dinv[s2], d3 = g_dinv[s3];
        float2 v0 = *reinterpret_cast<const float2*>(&hs[(size_t)s0 * C2 + lane * 2]);
        float2 v1 = *reinterpret_cast<const float2*>(&hs[(size_t)s1 * C2 + lane * 2]);
        float2 v2 = *reinterpret_cast<const float2*>(&hs[(size_t)s2 * C2 + lane * 2]);
        float2 v3 = *reinterpret_cast<const float2*>(&hs[(size_t)s3 * C2 + lane * 2]);
        acc.x += v0.x * d0 + v1.x * d1 + v2.x * d2 + v3.x * d3;
        acc.y += v0.y * d0 + v1.y * d1 + v2.y * d2 + v3.y * d3;
    }
    for (; k < e; k++) {
        int sk = g_srcidx[k];
        float dk = g_dinv[sk];
        float2 v = *reinterpret_cast<const float2*>(&hs[(size_t)sk * C2 + lane * 2]);
        acc.x += v.x * dk; acc.y += v.y * dk;
    }

    float2 b = *reinterpret_cast<const float2*>(&bias[lane * 2]);
    float2 o;
    o.x = dself * acc.x + b.x;
    o.y = dself * acc.y + b.y;
    if (RELU) { o.x = fmaxf(o.x, 0.f); o.y = fmaxf(o.y, 0.f); }
    *reinterpret_cast<float2*>(&out[(size_t)gw * C2 + lane * 2]) = o;
}

// ---------------- logits: out[e] = dot(z[qa], z[qb]) over C2=64 dims ----------------
__global__ void logits_kernel(int Q, const float* __restrict__ z, float* __restrict__ out) {
    long long idx = (long long)blockIdx.x * blockDim.x + threadIdx.x;
    long long e = idx / 16;
    int j       = (int)(idx % 16);
    if (e >= Q) return;
    int a = g_qa[e];
    int b = g_qb[e];
    float4 va = *reinterpret_cast<const float4*>(&z[(size_t)a * C2 + j * 4]);
    float4 vb = *reinterpret_cast<const float4*>(&z[(size_t)b * C2 + j * 4]);
    float d = va.x * vb.x + va.y * vb.y + va.z * vb.z + va.w * vb.w;
#pragma unroll
    for (int off = 8; off > 0; off >>= 1)
        d += __shfl_xor_sync(0xffffffffu, d, off, 16);
    if (j == 0) out[e] = d;
}

// ---------------- launch ----------------
extern "C" void kernel_launch(void* const* d_in, const int* in_sizes, int n_in,
                              void* d_out, int out_size) {
    const float* x   = (const float*)d_in[0];
    const void*  ei  = d_in[1];
    const void*  pos = d_in[2];
    const void*  neg = d_in[3];
    const float* W1  = (const float*)d_in[4];
    const float* b1  = (const float*)d_in[5];
    const float* W2  = (const float*)d_in[6];
    const float* b2  = (const float*)d_in[7];
    float* out = (float*)d_out;

    const int E  = in_sizes[1] / 2;   // 800000
    const int Ep = in_sizes[2] / 2;   // 200000
    const int En = in_sizes[3] / 2;   // 200000
    const int Q  = Ep + En;
    const int M  = N_NODES;

    float *hs1, *h, *hs2, *z;
    cudaGetSymbolAddress((void**)&hs1,  g_hs1);
    cudaGetSymbolAddress((void**)&h,    g_h);
    cudaGetSymbolAddress((void**)&hs2,  g_hs2);
    cudaGetSymbolAddress((void**)&z,    g_z);

    // launch index:                                                      // idx
    detect_kernel<<<1, 32>>>((const int*)ei);                             // 0
    zero_deg_kernel<<<(N_NODES + 255) / 256, 256>>>();                    // 1
    convert_edges_kernel<<<(E + 255) / 256, 256>>>(ei, E);                // 2
    // GEMM1 hoisted here (graph-independent) so the fixed ncu slot profiles it
    gemm_kernel<C1, CIN><<<(M + 127) / 128, 256>>>(x, W1, hs1, M);        // 3
    convert_queries_kernel<<<(Q + 255) / 256, 256>>>(pos, neg, Ep, En);   // 4
    dinv_kernel<<<(N_NODES + 255) / 256, 256>>>();                        // 5
    scan_kernel<<<1, 1024>>>();                                           // 6
    fill_kernel<<<(E + 255) / 256, 256>>>(E);                             // 7

    gather128_kernel<true><<<(N_NODES * 32 + 255) / 256, 256>>>(hs1, h, b1);   // 8
    gemm_kernel<C2, C1><<<(M + 127) / 128, 256>>>(h, W2, hs2, M);              // 9
    gather64_kernel<false><<<(N_NODES * 32 + 255) / 256, 256>>>(hs2, z, b2);   // 10

    {
        long long tot = (long long)Q * 16;
        int blocks = (int)((tot + 255) / 256);
        logits_kernel<<<blocks, 256>>>(Q, z, out);                        // 11
    }
}

// round 13
// speedup vs baseline: 1.6444x; 1.1364x over previous
#include <cuda_runtime.h>
#include <cuda_bf16.h>
#include <cstdint>

// ---------------- problem constants ----------------
#define N_NODES 50000
#define E_MAX   800000
#define Q_MAX   400000
constexpr int CIN  = 256;   // input channels
constexpr int C1   = 128;   // hidden channels
constexpr int C2   = 64;    // output channels
constexpr int NPAD = 50048; // 391 * 128 (padded rows for 128-row GEMM tiles)

// ---------------- device scratch (static; no allocs allowed) ----------------
__device__ int g_is64;
__device__ __align__(16) int   g_src   [E_MAX];
__device__ __align__(16) int   g_dst   [E_MAX];
__device__ __align__(16) int   g_qa    [Q_MAX];
__device__ __align__(16) int   g_qb    [Q_MAX];
__device__ __align__(16) int   g_deg   [N_NODES];
__device__ __align__(16) int   g_off   [N_NODES + 1];
__device__ __align__(16) int   g_cur   [N_NODES];
__device__ __align__(16) int   g_srcidx[E_MAX];
__device__ __align__(16) float g_dinv  [N_NODES];
// bf16 hi/lo split operands for tensor-core GEMMs
__device__ __align__(16) __nv_bfloat16 g_xhi [(size_t)NPAD * CIN];
__device__ __align__(16) __nv_bfloat16 g_xlo [(size_t)NPAD * CIN];
__device__ __align__(16) __nv_bfloat16 g_w1thi[(size_t)C1 * CIN];   // W1^T [C1][CIN]
__device__ __align__(16) __nv_bfloat16 g_w1tlo[(size_t)C1 * CIN];
__device__ __align__(16) __nv_bfloat16 g_hhi [(size_t)NPAD * C1];   // relu(h) split
__device__ __align__(16) __nv_bfloat16 g_hlo [(size_t)NPAD * C1];
__device__ __align__(16) __nv_bfloat16 g_w2thi[(size_t)C2 * C1];    // W2^T [C2][C1]
__device__ __align__(16) __nv_bfloat16 g_w2tlo[(size_t)C2 * C1];
// fp32 intermediates
__device__ __align__(16) float g_hs1[(size_t)NPAD * C1];   // x @ W1
__device__ __align__(16) float g_hs2[(size_t)NPAD * C2];   // h @ W2
__device__ __align__(16) float g_z  [(size_t)N_NODES * C2];

// ---------------- helpers ----------------
__device__ __forceinline__ uint32_t smem_u32(const void* p) {
    uint32_t a;
    asm("{ .reg .u64 t; cvta.to.shared.u64 t, %1; cvt.u32.u64 %0, t; }" : "=r"(a) : "l"(p));
    return a;
}
__device__ __forceinline__ uint32_t sw128(uint32_t off) { return off ^ ((off >> 3) & 0x70); }

__device__ __forceinline__ void ldsm_x4(uint32_t* r, uint32_t addr) {
    asm volatile("ldmatrix.sync.aligned.m8n8.x4.shared.b16 {%0,%1,%2,%3}, [%4];"
                 : "=r"(r[0]), "=r"(r[1]), "=r"(r[2]), "=r"(r[3]) : "r"(addr));
}
// D += A * B  (m16n8k16, bf16 inputs, fp32 accum)
__device__ __forceinline__ void mma_bf16(float* d, const uint32_t* a, const uint32_t* b) {
    asm volatile("mma.sync.aligned.m16n8k16.row.col.f32.bf16.bf16.f32 "
                 "{%0,%1,%2,%3}, {%4,%5,%6,%7}, {%8,%9}, {%0,%1,%2,%3};"
                 : "+f"(d[0]), "+f"(d[1]), "+f"(d[2]), "+f"(d[3])
                 : "r"(a[0]), "r"(a[1]), "r"(a[2]), "r"(a[3]), "r"(b[0]), "r"(b[1]));
}
__device__ __forceinline__ void split_bf16(float v, unsigned short& h, unsigned short& l) {
    __nv_bfloat16 bh = __float2bfloat16(v);
    __nv_bfloat16 bl = __float2bfloat16(v - __bfloat162float(bh));
    h = __bfloat16_as_ushort(bh);
    l = __bfloat16_as_ushort(bl);
}
__device__ __forceinline__ int clamp_idx(long long v) {
    if (v < 0) v = 0;
    if (v >= N_NODES) v = N_NODES - 1;
    return (int)v;
}

// ================= input normalization / CSR build (R11-proven) =================
__global__ void detect_kernel(const int* __restrict__ ei32) {
    int lane = threadIdx.x;
    int v = ei32[2 * lane + 1];
    unsigned nz = __ballot_sync(0xffffffffu, v != 0);
    if (lane == 0) g_is64 = (nz == 0u) ? 1 : 0;
}

__global__ void zero_deg_kernel() {
    int i = blockIdx.x * blockDim.x + threadIdx.x;
    if (i < N_NODES) g_deg[i] = 0;
}

__global__ void convert_edges_kernel(const void* __restrict__ ei, int E) {
    int e = blockIdx.x * blockDim.x + threadIdx.x;
    if (e >= E) return;
    int s, d;
    if (g_is64) {
        const long long* p = (const long long*)ei;
        s = clamp_idx(p[e]);
        d = clamp_idx(p[E + e]);
    } else {
        const int* p = (const int*)ei;
        s = clamp_idx(p[e]);
        d = clamp_idx(p[E + e]);
    }
    g_src[e] = s;
    g_dst[e] = d;
    atomicAdd(&g_deg[d], 1);
}

__global__ void convert_queries_kernel(const void* __restrict__ pos, const void* __restrict__ neg,
                                       int Ep, int En) {
    int i = blockIdx.x * blockDim.x + threadIdx.x;
    if (i >= Ep + En) return;
    int a, b;
    if (g_is64) {
        if (i < Ep) {
            const long long* p = (const long long*)pos;
            a = clamp_idx(p[i]);
            b = clamp_idx(p[Ep + i]);
        } else {
            const long long* p = (const long long*)neg;
            a = clamp_idx(p[i - Ep]);
            b = clamp_idx(p[En + i - Ep]);
        }
    } else {
        if (i < Ep) {
            const int* p = (const int*)pos;
            a = clamp_idx(p[i]);
            b = clamp_idx(p[Ep + i]);
        } else {
            const int* p = (const int*)neg;
            a = clamp_idx(p[i - Ep]);
            b = clamp_idx(p[En + i - Ep]);
        }
    }
    g_qa[i] = a;
    g_qb[i] = b;
}

__global__ void dinv_kernel() {
    int n = blockIdx.x * blockDim.x + threadIdx.x;
    if (n < N_NODES) g_dinv[n] = rsqrtf((float)(g_deg[n] + 1));
}

__global__ void __launch_bounds__(1024) scan_kernel() {
    __shared__ int wsum[32];
    __shared__ int s_carry;
    const int tid  = threadIdx.x;
    const int lane = tid & 31;
    const int wid  = tid >> 5;
    if (tid == 0) s_carry = 0;
    __syncthreads();
    for (int base = 0; base < N_NODES; base += 1024) {
        int i = base + tid;
        int v = (i < N_NODES) ? g_deg[i] : 0;
        int inc = v;
#pragma unroll
        for (int o = 1; o < 32; o <<= 1) {
            int t = __shfl_up_sync(0xffffffffu, inc, o);
            if (lane >= o) inc += t;
        }
        if (lane == 31) wsum[wid] = inc;
        __syncthreads();
        if (wid == 0) {
            int w = wsum[lane];
            int winc = w;
#pragma unroll
            for (int o = 1; o < 32; o <<= 1) {
                int t = __shfl_up_sync(0xffffffffu, winc, o);
                if (lane >= o) winc += t;
            }
            wsum[lane] = winc;
        }
        __syncthreads();
        int excl = s_carry + ((wid > 0) ? wsum[wid - 1] : 0) + inc - v;
        if (i < N_NODES) { g_off[i] = excl; g_cur[i] = excl; }
        int chunk_total = wsum[31];
        __syncthreads();
        if (tid == 0) s_carry += chunk_total;
        __syncthreads();
    }
    if (threadIdx.x == 0) g_off[N_NODES] = s_carry;
}

__global__ void fill_kernel(int E) {
    int e = blockIdx.x * blockDim.x + threadIdx.x;
    if (e < E) {
        int pos = atomicAdd(&g_cur[g_dst[e]], 1);
        g_srcidx[pos] = g_src[e];
    }
}

// ================= bf16 split conversions =================
__global__ void split_x_kernel(const float* __restrict__ x) {
    size_t i = (size_t)blockIdx.x * blockDim.x + threadIdx.x;
    if (i >= (size_t)NPAD * CIN / 4) return;
    size_t row = i / (CIN / 4);
    float4 v = make_float4(0.f, 0.f, 0.f, 0.f);
    if (row < N_NODES) v = reinterpret_cast<const float4*>(x)[i];
    ushort4 h, l;
    split_bf16(v.x, h.x, l.x);
    split_bf16(v.y, h.y, l.y);
    split_bf16(v.z, h.z, l.z);
    split_bf16(v.w, h.w, l.w);
    reinterpret_cast<ushort4*>(g_xhi)[i] = h;
    reinterpret_cast<ushort4*>(g_xlo)[i] = l;
}

template <int K, int N>
__global__ void split_wt_kernel(const float* __restrict__ W,
                                __nv_bfloat16* __restrict__ hi, __nv_bfloat16* __restrict__ lo) {
    int i = blockIdx.x * blockDim.x + threadIdx.x;
    if (i >= K * N) return;
    int n = i / K, k = i % K;
    unsigned short h, l;
    split_bf16(W[(size_t)k * N + n], h, l);
    hi[(size_t)n * K + k] = __ushort_as_bfloat16(h);
    lo[(size_t)n * K + k] = __ushort_as_bfloat16(l);
}

// ================= HMMA GEMM: out[NPAD, N_DIM] = A @ B^T =================
// A: [NPAD, K_DIM] bf16 hi/lo, B: [N_DIM, K_DIM] bf16 hi/lo, out fp32.
// 3 accumulate passes: Ah*Bh + Ah*Bl + Al*Bh (one shared fp32 accumulator).
// CTA: 128 rows, 256 threads = 8 warps; warp w owns rows [w*16, w*16+16).
template <int N_DIM, int K_DIM>
__global__ void __launch_bounds__(256)
mma_gemm_kernel(const __nv_bfloat16* __restrict__ a_hi, const __nv_bfloat16* __restrict__ a_lo,
                const __nv_bfloat16* __restrict__ b_hi, const __nv_bfloat16* __restrict__ b_lo,
                float* __restrict__ out) {
    constexpr int NCHUNK = K_DIM / 64;       // k staged 64 wide (128 B/row, SW128 atom)
    constexpr int NT     = N_DIM / 8;        // n-tiles per warp (full N)
    constexpr int A_TILE = 128 * 128;        // bytes
    constexpr int B_TILE = N_DIM * 128;
    constexpr int S_A_HI = 0;
    constexpr int S_A_LO = A_TILE;
    constexpr int S_B_HI = 2 * A_TILE;
    constexpr int S_B_LO = 2 * A_TILE + B_TILE;

    extern __shared__ char smem[];
    const uint32_t sbase = smem_u32(smem);
    const int tid  = threadIdx.x;
    const int wid  = tid >> 5;
    const int lane = tid & 31;
    const int row0 = blockIdx.x * 128;

    float acc[NT][4];
#pragma unroll
    for (int t = 0; t < NT; t++)
#pragma unroll
        for (int c = 0; c < 4; c++) acc[t][c] = 0.f;

    // ldmatrix lane-address components (within-tile)
    const int g = lane >> 3, l8 = lane & 7;
    // A x4: m0 rows0-7/k0, m1 rows8-15/k0, m2 rows0-7/k+8, m3 rows8-15/k+8
    const int a_row = wid * 16 + l8 + ((g & 1) ? 8 : 0);
    const int a_k8  = (g >> 1) ? 8 : 0;
    // B x4 (2 n-tiles): m0 n0-7/k0, m1 n0-7/k+8, m2 n8-15/k0, m3 n8-15/k+8
    const int b_nrel = l8 + ((g >> 1) ? 8 : 0);
    const int b_k8   = (g & 1) ? 8 : 0;

    constexpr int KU4 = K_DIM / 8;           // uint4 per global row

    for (int kc = 0; kc < NCHUNK; kc++) {
        if (kc > 0) __syncthreads();         // drain consumers before overwrite
        // stage A hi/lo: 1024 uint4 each, 256 threads -> 4 iters
#pragma unroll
        for (int li = 0; li < 4; li++) {
            int f = tid + li * 256;
            int r = f >> 3, c16 = f & 7;
            uint32_t sw = sw128((uint32_t)(r * 128 + c16 * 16));
            size_t gi = (size_t)(row0 + r) * KU4 + (size_t)kc * 8 + c16;
            *reinterpret_cast<uint4*>(smem + S_A_HI + sw) = reinterpret_cast<const uint4*>(a_hi)[gi];
            *reinterpret_cast<uint4*>(smem + S_A_LO + sw) = reinterpret_cast<const uint4*>(a_lo)[gi];
        }
        // stage B hi/lo: N_DIM*8 uint4 each
#pragma unroll
        for (int f = tid; f < N_DIM * 8; f += 256) {
            int n = f >> 3, c16 = f & 7;
            uint32_t sw = sw128((uint32_t)(n * 128 + c16 * 16));
            size_t gi = (size_t)n * KU4 + (size_t)kc * 8 + c16;
            *reinterpret_cast<uint4*>(smem + S_B_HI + sw) = reinterpret_cast<const uint4*>(b_hi)[gi];
            *reinterpret_cast<uint4*>(smem + S_B_LO + sw) = reinterpret_cast<const uint4*>(b_lo)[gi];
        }
        __syncthreads();

#pragma unroll
        for (int ks = 0; ks < 4; ks++) {     // 4 k-steps of 16 within the 64 chunk
            uint32_t ah[4], al[4];
            uint32_t a_off = sw128((uint32_t)(a_row * 128 + (ks * 16 + a_k8) * 2));
            ldsm_x4(ah, sbase + S_A_HI + a_off);
            ldsm_x4(al, sbase + S_A_LO + a_off);
#pragma unroll
            for (int np = 0; np < NT / 2; np++) {
                uint32_t bh[4], bl[4];
                uint32_t b_off = sw128((uint32_t)((np * 16 + b_nrel) * 128 + (ks * 16 + b_k8) * 2));
                ldsm_x4(bh, sbase + S_B_HI + b_off);
                ldsm_x4(bl, sbase + S_B_LO + b_off);
                mma_bf16(acc[2 * np],     ah, bh);        // hh, tile n0
                mma_bf16(acc[2 * np + 1], ah, bh + 2);    // hh, tile n0+8
                mma_bf16(acc[2 * np],     ah, bl);        // hl
                mma_bf16(acc[2 * np + 1], ah, bl + 2);
                mma_bf16(acc[2 * np],     al, bh);        // lh
                mma_bf16(acc[2 * np + 1], al, bh + 2);
            }
        }
    }

    // epilogue: D layout c0/c1 at (lane/4, 2*(lane%4)), c2/c3 at row+8
    const size_t rlo  = (size_t)row0 + wid * 16 + (lane >> 2);
    const int    col0 = (lane & 3) * 2;
#pragma unroll
    for (int nt = 0; nt < NT; nt++) {
        float2 v0 = make_float2(acc[nt][0], acc[nt][1]);
        float2 v1 = make_float2(acc[nt][2], acc[nt][3]);
        *reinterpret_cast<float2*>(&out[rlo * N_DIM + nt * 8 + col0])       = v0;
        *reinterpret_cast<float2*>(&out[(rlo + 8) * N_DIM + nt * 8 + col0]) = v1;
    }
}

// ================= gather + combine =================
// C=128: one warp per node; emits bf16 hi/lo split of relu output (GEMM2 operand)
__global__ void gather128_kernel(const float* __restrict__ hs,
                                 const float* __restrict__ bias) {
    int gw   = (blockIdx.x * blockDim.x + threadIdx.x) >> 5;
    int lane = threadIdx.x & 31;
    if (gw >= NPAD) return;
    ushort4* hrow = reinterpret_cast<ushort4*>(g_hhi + (size_t)gw * C1);
    ushort4* lrow = reinterpret_cast<ushort4*>(g_hlo + (size_t)gw * C1);
    if (gw >= N_NODES) {
        ushort4 zz = make_ushort4(0, 0, 0, 0);
        hrow[lane] = zz;
        lrow[lane] = zz;
        return;
    }
    const int s = g_off[gw];
    const int e = g_off[gw + 1];
    const float dself = g_dinv[gw];

    float4 self = *reinterpret_cast<const float4*>(&hs[(size_t)gw * C1 + lane * 4]);
    float4 acc;
    acc.x = self.x * dself;
    acc.y = self.y * dself;
    acc.z = self.z * dself;
    acc.w = self.w * dself;

    int k = s;
    for (; k + 4 <= e; k += 4) {
        int s0 = g_srcidx[k + 0];
        int s1 = g_srcidx[k + 1];
        int s2 = g_srcidx[k + 2];
        int s3 = g_srcidx[k + 3];
        float d0 = g_dinv[s0], d1 = g_dinv[s1], d2 = g_dinv[s2], d3 = g_dinv[s3];
        float4 v0 = *reinterpret_cast<const float4*>(&hs[(size_t)s0 * C1 + lane * 4]);
        float4 v1 = *reinterpret_cast<const float4*>(&hs[(size_t)s1 * C1 + lane * 4]);
        float4 v2 = *reinterpret_cast<const float4*>(&hs[(size_t)s2 * C1 + lane * 4]);
        float4 v3 = *reinterpret_cast<const float4*>(&hs[(size_t)s3 * C1 + lane * 4]);
        acc.x += v0.x * d0 + v1.x * d1 + v2.x * d2 + v3.x * d3;
        acc.y += v0.y * d0 + v1.y * d1 + v2.y * d2 + v3.y * d3;
        acc.z += v0.z * d0 + v1.z * d1 + v2.z * d2 + v3.z * d3;
        acc.w += v0.w * d0 + v1.w * d1 + v2.w * d2 + v3.w * d3;
    }
    for (; k < e; k++) {
        int sk = g_srcidx[k];
        float dk = g_dinv[sk];
        float4 v = *reinterpret_cast<const float4*>(&hs[(size_t)sk * C1 + lane * 4]);
        acc.x += v.x * dk; acc.y += v.y * dk; acc.z += v.z * dk; acc.w += v.w * dk;
    }

    float4 b = *reinterpret_cast<const float4*>(&bias[lane * 4]);
    float4 o;
    o.x = fmaxf(dself * acc.x + b.x, 0.f);
    o.y = fmaxf(dself * acc.y + b.y, 0.f);
    o.z = fmaxf(dself * acc.z + b.z, 0.f);
    o.w = fmaxf(dself * acc.w + b.w, 0.f);

    ushort4 hv, lv;
    split_bf16(o.x, hv.x, lv.x);
    split_bf16(o.y, hv.y, lv.y);
    split_bf16(o.z, hv.z, lv.z);
    split_bf16(o.w, hv.w, lv.w);
    hrow[lane] = hv;
    lrow[lane] = lv;
}

// C=64: one warp per node, float2 per lane, fp32 output
__global__ void gather64_kernel(const float* __restrict__ hs, float* __restrict__ out,
                                const float* __restrict__ bias) {
    int gw   = (blockIdx.x * blockDim.x + threadIdx.x) >> 5;
    int lane = threadIdx.x & 31;
    if (gw >= N_NODES) return;
    const int s = g_off[gw];
    const int e = g_off[gw + 1];
    const float dself = g_dinv[gw];

    float2 self = *reinterpret_cast<const float2*>(&hs[(size_t)gw * C2 + lane * 2]);
    float2 acc;
    acc.x = self.x * dself;
    acc.y = self.y * dself;

    int k = s;
    for (; k + 4 <= e; k += 4) {
        int s0 = g_srcidx[k + 0];
        int s1 = g_srcidx[k + 1];
        int s2 = g_srcidx[k + 2];
        int s3 = g_srcidx[k + 3];
        float d0 = g_dinv[s0], d1 = g_dinv[s1], d2 = g_dinv[s2], d3 = g_dinv[s3];
        float2 v0 = *reinterpret_cast<const float2*>(&hs[(size_t)s0 * C2 + lane * 2]);
        float2 v1 = *reinterpret_cast<const float2*>(&hs[(size_t)s1 * C2 + lane * 2]);
        float2 v2 = *reinterpret_cast<const float2*>(&hs[(size_t)s2 * C2 + lane * 2]);
        float2 v3 = *reinterpret_cast<const float2*>(&hs[(size_t)s3 * C2 + lane * 2]);
        acc.x += v0.x * d0 + v1.x * d1 + v2.x * d2 + v3.x * d3;
        acc.y += v0.y * d0 + v1.y * d1 + v2.y * d2 + v3.y * d3;
    }
    for (; k < e; k++) {
        int sk = g_srcidx[k];
        float dk = g_dinv[sk];
        float2 v = *reinterpret_cast<const float2*>(&hs[(size_t)sk * C2 + lane * 2]);
        acc.x += v.x * dk; acc.y += v.y * dk;
    }

    float2 b = *reinterpret_cast<const float2*>(&bias[lane * 2]);
    float2 o;
    o.x = dself * acc.x + b.x;
    o.y = dself * acc.y + b.y;
    *reinterpret_cast<float2*>(&out[(size_t)gw * C2 + lane * 2]) = o;
}

// ---------------- logits ----------------
__global__ void logits_kernel(int Q, const float* __restrict__ z, float* __restrict__ out) {
    long long idx = (long long)blockIdx.x * blockDim.x + threadIdx.x;
    long long e = idx / 16;
    int j       = (int)(idx % 16);
    if (e >= Q) return;
    int a = g_qa[e];
    int b = g_qb[e];
    float4 va = *reinterpret_cast<const float4*>(&z[(size_t)a * C2 + j * 4]);
    float4 vb = *reinterpret_cast<const float4*>(&z[(size_t)b * C2 + j * 4]);
    float d = va.x * vb.x + va.y * vb.y + va.z * vb.z + va.w * vb.w;
#pragma unroll
    for (int off = 8; off > 0; off >>= 1)
        d += __shfl_xor_sync(0xffffffffu, d, off, 16);
    if (j == 0) out[e] = d;
}

// ---------------- launch ----------------
extern "C" void kernel_launch(void* const* d_in, const int* in_sizes, int n_in,
                              void* d_out, int out_size) {
    const float* x   = (const float*)d_in[0];
    const void*  ei  = d_in[1];
    const void*  pos = d_in[2];
    const void*  neg = d_in[3];
    const float* W1  = (const float*)d_in[4];
    const float* b1  = (const float*)d_in[5];
    const float* W2  = (const float*)d_in[6];
    const float* b2  = (const float*)d_in[7];
    float* out = (float*)d_out;

    const int E  = in_sizes[1] / 2;
    const int Ep = in_sizes[2] / 2;
    const int En = in_sizes[3] / 2;
    const int Q  = Ep + En;

    float *hs1, *hs2, *z;
    __nv_bfloat16 *xhi, *xlo, *w1thi, *w1tlo, *hhi, *hlo, *w2thi, *w2tlo;
    cudaGetSymbolAddress((void**)&hs1,   g_hs1);
    cudaGetSymbolAddress((void**)&hs2,   g_hs2);
    cudaGetSymbolAddress((void**)&z,     g_z);
    cudaGetSymbolAddress((void**)&xhi,   g_xhi);
    cudaGetSymbolAddress((void**)&xlo,   g_xlo);
    cudaGetSymbolAddress((void**)&w1thi, g_w1thi);
    cudaGetSymbolAddress((void**)&w1tlo, g_w1tlo);
    cudaGetSymbolAddress((void**)&hhi,   g_hhi);
    cudaGetSymbolAddress((void**)&hlo,   g_hlo);
    cudaGetSymbolAddress((void**)&w2thi, g_w2thi);
    cudaGetSymbolAddress((void**)&w2tlo, g_w2tlo);

    constexpr int SMEM1 = 2 * (128 * 128) + 2 * (C1 * 128);  // 65536
    constexpr int SMEM2 = 2 * (128 * 128) + 2 * (C2 * 128);  // 49152
    cudaFuncSetAttribute(mma_gemm_kernel<C1, CIN>, cudaFuncAttributeMaxDynamicSharedMemorySize, SMEM1);
    cudaFuncSetAttribute(mma_gemm_kernel<C2, C1>,  cudaFuncAttributeMaxDynamicSharedMemorySize, SMEM2);

    const int NTILES = NPAD / 128;   // 391

    // launch order (GEMM1 at index 3 = the ncu-profiled slot)
    {
        size_t n = (size_t)NPAD * CIN / 4;
        split_x_kernel<<<(int)((n + 255) / 256), 256>>>(x);                        // 0
    }
    split_wt_kernel<CIN, C1><<<(CIN * C1 + 255) / 256, 256>>>(W1, w1thi, w1tlo);   // 1
    detect_kernel<<<1, 32>>>((const int*)ei);                                       // 2
    mma_gemm_kernel<C1, CIN><<<NTILES, 256, SMEM1>>>(xhi, xlo, w1thi, w1tlo, hs1); // 3
    zero_deg_kernel<<<(N_NODES + 255) / 256, 256>>>();                              // 4
    convert_edges_kernel<<<(E + 255) / 256, 256>>>(ei, E);                          // 5
    convert_queries_kernel<<<(Q + 255) / 256, 256>>>(pos, neg, Ep, En);             // 6
    dinv_kernel<<<(N_NODES + 255) / 256, 256>>>();                                  // 7
    scan_kernel<<<1, 1024>>>();                                                     // 8
    fill_kernel<<<(E + 255) / 256, 256>>>(E);                                       // 9
    split_wt_kernel<C1, C2><<<(C1 * C2 + 255) / 256, 256>>>(W2, w2thi, w2tlo);      // 10
    gather128_kernel<<<(NPAD * 32 + 255) / 256, 256>>>(hs1, b1);                    // 11
    mma_gemm_kernel<C2, C1><<<NTILES, 256, SMEM2>>>(hhi, hlo, w2thi, w2tlo, hs2);   // 12
    gather64_kernel<<<(N_NODES * 32 + 255) / 256, 256>>>(hs2, z, b2);               // 13
    {
        long long tot = (long long)Q * 16;
        logits_kernel<<<(int)((tot + 255) / 256), 256>>>(Q, z, out);                // 14
    }
}

// round 14
// speedup vs baseline: 1.8195x; 1.1065x over previous
#include <cuda_runtime.h>
#include <cuda_bf16.h>
#include <cstdint>

// ---------------- problem constants ----------------
#define N_NODES 50000
#define E_MAX   800000
#define Q_MAX   400000
constexpr int CIN  = 256;   // input channels
constexpr int C1   = 128;   // hidden channels
constexpr int C2   = 64;    // output channels
constexpr int NPAD = 50048; // 391 * 128 (padded rows for 128-row GEMM tiles)

// ---------------- device scratch (static; no allocs allowed) ----------------
__device__ int g_is64;
__device__ __align__(16) int   g_src   [E_MAX];
__device__ __align__(16) int   g_dst   [E_MAX];
__device__ __align__(16) int   g_qa    [Q_MAX];
__device__ __align__(16) int   g_qb    [Q_MAX];
__device__ __align__(16) int   g_deg   [N_NODES];
__device__ __align__(16) int   g_off   [N_NODES + 1];
__device__ __align__(16) int   g_cur   [N_NODES];
__device__ __align__(16) int   g_srcidx[E_MAX];
__device__ __align__(16) float g_dinv  [N_NODES];
// bf16 hi/lo split operands for tensor-core GEMMs
__device__ __align__(16) __nv_bfloat16 g_xhi [(size_t)NPAD * CIN];
__device__ __align__(16) __nv_bfloat16 g_xlo [(size_t)NPAD * CIN];
__device__ __align__(16) __nv_bfloat16 g_w1thi[(size_t)C1 * CIN];   // W1^T [C1][CIN]
__device__ __align__(16) __nv_bfloat16 g_w1tlo[(size_t)C1 * CIN];
__device__ __align__(16) __nv_bfloat16 g_hhi [(size_t)NPAD * C1];   // relu(h) split
__device__ __align__(16) __nv_bfloat16 g_hlo [(size_t)NPAD * C1];
__device__ __align__(16) __nv_bfloat16 g_w2thi[(size_t)C2 * C1];    // W2^T [C2][C1]
__device__ __align__(16) __nv_bfloat16 g_w2tlo[(size_t)C2 * C1];
// fp32 intermediates
__device__ __align__(16) float g_hs1[(size_t)NPAD * C1];   // x @ W1
__device__ __align__(16) float g_hs2[(size_t)NPAD * C2];   // h @ W2
__device__ __align__(16) float g_z  [(size_t)N_NODES * C2];

// ---------------- helpers ----------------
__device__ __forceinline__ uint32_t smem_u32(const void* p) {
    uint32_t a;
    asm("{ .reg .u64 t; cvta.to.shared.u64 t, %1; cvt.u32.u64 %0, t; }" : "=r"(a) : "l"(p));
    return a;
}
__device__ __forceinline__ uint32_t sw128(uint32_t off) { return off ^ ((off >> 3) & 0x70); }

__device__ __forceinline__ void ldsm_x4(uint32_t* r, uint32_t addr) {
    asm volatile("ldmatrix.sync.aligned.m8n8.x4.shared.b16 {%0,%1,%2,%3}, [%4];"
                 : "=r"(r[0]), "=r"(r[1]), "=r"(r[2]), "=r"(r[3]) : "r"(addr));
}
// D += A * B  (m16n8k16, bf16 inputs, fp32 accum)
__device__ __forceinline__ void mma_bf16(float* d, const uint32_t* a, const uint32_t* b) {
    asm volatile("mma.sync.aligned.m16n8k16.row.col.f32.bf16.bf16.f32 "
                 "{%0,%1,%2,%3}, {%4,%5,%6,%7}, {%8,%9}, {%0,%1,%2,%3};"
                 : "+f"(d[0]), "+f"(d[1]), "+f"(d[2]), "+f"(d[3])
                 : "r"(a[0]), "r"(a[1]), "r"(a[2]), "r"(a[3]), "r"(b[0]), "r"(b[1]));
}
// async 16B copy global -> shared (sm_80 baseline)
#define CP_ASYNC16(dst_u32, src_ptr) \
    asm volatile("cp.async.cg.shared.global [%0], [%1], 16;" :: "r"(dst_u32), "l"(src_ptr))
#define CP_COMMIT() asm volatile("cp.async.commit_group;" ::: "memory")
#define CP_WAIT(n)  asm volatile("cp.async.wait_group %0;" :: "n"(n) : "memory")

__device__ __forceinline__ void split_bf16(float v, unsigned short& h, unsigned short& l) {
    __nv_bfloat16 bh = __float2bfloat16(v);
    __nv_bfloat16 bl = __float2bfloat16(v - __bfloat162float(bh));
    h = __bfloat16_as_ushort(bh);
    l = __bfloat16_as_ushort(bl);
}
__device__ __forceinline__ int clamp_idx(long long v) {
    if (v < 0) v = 0;
    if (v >= N_NODES) v = N_NODES - 1;
    return (int)v;
}

// ================= input normalization / CSR build (R11-proven) =================
__global__ void detect_kernel(const int* __restrict__ ei32) {
    int lane = threadIdx.x;
    int v = ei32[2 * lane + 1];
    unsigned nz = __ballot_sync(0xffffffffu, v != 0);
    if (lane == 0) g_is64 = (nz == 0u) ? 1 : 0;
}

__global__ void zero_deg_kernel() {
    int i = blockIdx.x * blockDim.x + threadIdx.x;
    if (i < N_NODES) g_deg[i] = 0;
}

__global__ void convert_edges_kernel(const void* __restrict__ ei, int E) {
    int e = blockIdx.x * blockDim.x + threadIdx.x;
    if (e >= E) return;
    int s, d;
    if (g_is64) {
        const long long* p = (const long long*)ei;
        s = clamp_idx(p[e]);
        d = clamp_idx(p[E + e]);
    } else {
        const int* p = (const int*)ei;
        s = clamp_idx(p[e]);
        d = clamp_idx(p[E + e]);
    }
    g_src[e] = s;
    g_dst[e] = d;
    atomicAdd(&g_deg[d], 1);
}

__global__ void convert_queries_kernel(const void* __restrict__ pos, const void* __restrict__ neg,
                                       int Ep, int En) {
    int i = blockIdx.x * blockDim.x + threadIdx.x;
    if (i >= Ep + En) return;
    int a, b;
    if (g_is64) {
        if (i < Ep) {
            const long long* p = (const long long*)pos;
            a = clamp_idx(p[i]);
            b = clamp_idx(p[Ep + i]);
        } else {
            const long long* p = (const long long*)neg;
            a = clamp_idx(p[i - Ep]);
            b = clamp_idx(p[En + i - Ep]);
        }
    } else {
        if (i < Ep) {
            const int* p = (const int*)pos;
            a = clamp_idx(p[i]);
            b = clamp_idx(p[Ep + i]);
        } else {
            const int* p = (const int*)neg;
            a = clamp_idx(p[i - Ep]);
            b = clamp_idx(p[En + i - Ep]);
        }
    }
    g_qa[i] = a;
    g_qb[i] = b;
}

__global__ void dinv_kernel() {
    int n = blockIdx.x * blockDim.x + threadIdx.x;
    if (n < N_NODES) g_dinv[n] = rsqrtf((float)(g_deg[n] + 1));
}

__global__ void __launch_bounds__(1024) scan_kernel() {
    __shared__ int wsum[32];
    __shared__ int s_carry;
    const int tid  = threadIdx.x;
    const int lane = tid & 31;
    const int wid  = tid >> 5;
    if (tid == 0) s_carry = 0;
    __syncthreads();
    for (int base = 0; base < N_NODES; base += 1024) {
        int i = base + tid;
        int v = (i < N_NODES) ? g_deg[i] : 0;
        int inc = v;
#pragma unroll
        for (int o = 1; o < 32; o <<= 1) {
            int t = __shfl_up_sync(0xffffffffu, inc, o);
            if (lane >= o) inc += t;
        }
        if (lane == 31) wsum[wid] = inc;
        __syncthreads();
        if (wid == 0) {
            int w = wsum[lane];
            int winc = w;
#pragma unroll
            for (int o = 1; o < 32; o <<= 1) {
                int t = __shfl_up_sync(0xffffffffu, winc, o);
                if (lane >= o) winc += t;
            }
            wsum[lane] = winc;
        }
        __syncthreads();
        int excl = s_carry + ((wid > 0) ? wsum[wid - 1] : 0) + inc - v;
        if (i < N_NODES) { g_off[i] = excl; g_cur[i] = excl; }
        int chunk_total = wsum[31];
        __syncthreads();
        if (tid == 0) s_carry += chunk_total;
        __syncthreads();
    }
    if (threadIdx.x == 0) g_off[N_NODES] = s_carry;
}

__global__ void fill_kernel(int E) {
    int e = blockIdx.x * blockDim.x + threadIdx.x;
    if (e < E) {
        int pos = atomicAdd(&g_cur[g_dst[e]], 1);
        g_srcidx[pos] = g_src[e];
    }
}

// ================= bf16 split conversions =================
__global__ void split_x_kernel(const float* __restrict__ x) {
    size_t i = (size_t)blockIdx.x * blockDim.x + threadIdx.x;
    if (i >= (size_t)NPAD * CIN / 4) return;
    size_t row = i / (CIN / 4);
    float4 v = make_float4(0.f, 0.f, 0.f, 0.f);
    if (row < N_NODES) v = reinterpret_cast<const float4*>(x)[i];
    ushort4 h, l;
    split_bf16(v.x, h.x, l.x);
    split_bf16(v.y, h.y, l.y);
    split_bf16(v.z, h.z, l.z);
    split_bf16(v.w, h.w, l.w);
    reinterpret_cast<ushort4*>(g_xhi)[i] = h;
    reinterpret_cast<ushort4*>(g_xlo)[i] = l;
}

template <int K, int N>
__global__ void split_wt_kernel(const float* __restrict__ W,
                                __nv_bfloat16* __restrict__ hi, __nv_bfloat16* __restrict__ lo) {
    int i = blockIdx.x * blockDim.x + threadIdx.x;
    if (i >= K * N) return;
    int n = i / K, k = i % K;
    unsigned short h, l;
    split_bf16(W[(size_t)k * N + n], h, l);
    hi[(size_t)n * K + k] = __ushort_as_bfloat16(h);
    lo[(size_t)n * K + k] = __ushort_as_bfloat16(l);
}

// ================= HMMA GEMM (cp.async double-buffered) =================
// out[NPAD, N_DIM] = A @ B^T. A: [NPAD, K_DIM] bf16 hi/lo, B: [N_DIM, K_DIM] bf16 hi/lo.
// 3 accumulate passes: Ah*Bh + Ah*Bl + Al*Bh.
// CTA: 128 rows, 256 threads = 8 warps; warp w owns rows [w*16, w*16+16).
template <int N_DIM, int K_DIM>
__global__ void __launch_bounds__(256)
mma_gemm_kernel(const __nv_bfloat16* __restrict__ a_hi, const __nv_bfloat16* __restrict__ a_lo,
                const __nv_bfloat16* __restrict__ b_hi, const __nv_bfloat16* __restrict__ b_lo,
                float* __restrict__ out) {
    constexpr int NCHUNK = K_DIM / 64;       // k staged 64 wide (128 B/row, SW128 atom)
    constexpr int NT     = N_DIM / 8;        // n-tiles per warp (full N)
    constexpr int A_TILE = 128 * 128;        // bytes per A buffer (hi or lo)
    constexpr int B_TILE = N_DIM * 128;
    constexpr int S_A_HI = 0;
    constexpr int S_A_LO = A_TILE;
    constexpr int S_B_HI = 2 * A_TILE;
    constexpr int S_B_LO = 2 * A_TILE + B_TILE;
    constexpr int STAGE  = 2 * A_TILE + 2 * B_TILE;

    extern __shared__ char smem[];
    const uint32_t sbase = smem_u32(smem);
    const int tid  = threadIdx.x;
    const int wid  = tid >> 5;
    const int lane = tid & 31;
    const int row0 = blockIdx.x * 128;

    float acc[NT][4];
#pragma unroll
    for (int t = 0; t < NT; t++)
#pragma unroll
        for (int c = 0; c < 4; c++) acc[t][c] = 0.f;

    // ldmatrix lane-address components (within-tile)
    const int g = lane >> 3, l8 = lane & 7;
    const int a_row = wid * 16 + l8 + ((g & 1) ? 8 : 0);
    const int a_k8  = (g >> 1) ? 8 : 0;
    const int b_nrel = l8 + ((g >> 1) ? 8 : 0);
    const int b_k8   = (g & 1) ? 8 : 0;

    constexpr int KU4 = K_DIM / 8;           // uint4 per global row

    // async staging of one k-chunk into a buffer
    auto stage = [&](int kc, int buf) {
        const uint32_t SB = sbase + buf * STAGE;
#pragma unroll
        for (int li = 0; li < 4; li++) {
            int f = tid + li * 256;
            int r = f >> 3, c16 = f & 7;
            uint32_t sw = sw128((uint32_t)(r * 128 + c16 * 16));
            size_t gi = (size_t)(row0 + r) * KU4 + (size_t)kc * 8 + c16;
            CP_ASYNC16(SB + S_A_HI + sw, reinterpret_cast<const uint4*>(a_hi) + gi);
            CP_ASYNC16(SB + S_A_LO + sw, reinterpret_cast<const uint4*>(a_lo) + gi);
        }
#pragma unroll
        for (int f = tid; f < N_DIM * 8; f += 256) {
            int n = f >> 3, c16 = f & 7;
            uint32_t sw = sw128((uint32_t)(n * 128 + c16 * 16));
            size_t gi = (size_t)n * KU4 + (size_t)kc * 8 + c16;
            CP_ASYNC16(SB + S_B_HI + sw, reinterpret_cast<const uint4*>(b_hi) + gi);
            CP_ASYNC16(SB + S_B_LO + sw, reinterpret_cast<const uint4*>(b_lo) + gi);
        }
        CP_COMMIT();
    };

    stage(0, 0);

    for (int kc = 0; kc < NCHUNK; kc++) {
        const int buf = kc & 1;
        if (kc > 0) __syncthreads();            // prior compute done before its buffer is overwritten
        if (kc + 1 < NCHUNK) {
            stage(kc + 1, buf ^ 1);
            CP_WAIT(1);                          // chunk kc resident; kc+1 in flight
        } else {
            CP_WAIT(0);
        }
        __syncthreads();

        const uint32_t SB = sbase + buf * STAGE;
#pragma unroll
        for (int ks = 0; ks < 4; ks++) {         // 4 k-steps of 16 within the 64 chunk
            uint32_t ah[4], al[4];
            uint32_t a_off = sw128((uint32_t)(a_row * 128 + (ks * 16 + a_k8) * 2));
            ldsm_x4(ah, SB + S_A_HI + a_off);
            ldsm_x4(al, SB + S_A_LO + a_off);
#pragma unroll
            for (int np = 0; np < NT / 2; np++) {
                uint32_t bh[4], bl[4];
                uint32_t b_off = sw128((uint32_t)((np * 16 + b_nrel) * 128 + (ks * 16 + b_k8) * 2));
                ldsm_x4(bh, SB + S_B_HI + b_off);
                ldsm_x4(bl, SB + S_B_LO + b_off);
                mma_bf16(acc[2 * np],     ah, bh);        // hh, tile n0
                mma_bf16(acc[2 * np + 1], ah, bh + 2);    // hh, tile n0+8
                mma_bf16(acc[2 * np],     ah, bl);        // hl
                mma_bf16(acc[2 * np + 1], ah, bl + 2);
                mma_bf16(acc[2 * np],     al, bh);        // lh
                mma_bf16(acc[2 * np + 1], al, bh + 2);
            }
        }
    }

    // epilogue: D layout c0/c1 at (lane/4, 2*(lane%4)), c2/c3 at row+8
    const size_t rlo  = (size_t)row0 + wid * 16 + (lane >> 2);
    const int    col0 = (lane & 3) * 2;
#pragma unroll
    for (int nt = 0; nt < NT; nt++) {
        float2 v0 = make_float2(acc[nt][0], acc[nt][1]);
        float2 v1 = make_float2(acc[nt][2], acc[nt][3]);
        *reinterpret_cast<float2*>(&out[rlo * N_DIM + nt * 8 + col0])       = v0;
        *reinterpret_cast<float2*>(&out[(rlo + 8) * N_DIM + nt * 8 + col0]) = v1;
    }
}

// ================= gather + combine =================
// C=128: one warp per node; emits bf16 hi/lo split of relu output (GEMM2 operand)
__global__ void gather128_kernel(const float* __restrict__ hs,
                                 const float* __restrict__ bias) {
    int gw   = (blockIdx.x * blockDim.x + threadIdx.x) >> 5;
    int lane = threadIdx.x & 31;
    if (gw >= NPAD) return;
    ushort4* hrow = reinterpret_cast<ushort4*>(g_hhi + (size_t)gw * C1);
    ushort4* lrow = reinterpret_cast<ushort4*>(g_hlo + (size_t)gw * C1);
    if (gw >= N_NODES) {
        ushort4 zz = make_ushort4(0, 0, 0, 0);
        hrow[lane] = zz;
        lrow[lane] = zz;
        return;
    }
    const int s = g_off[gw];
    const int e = g_off[gw + 1];
    const float dself = g_dinv[gw];

    float4 self = *reinterpret_cast<const float4*>(&hs[(size_t)gw * C1 + lane * 4]);
    float4 acc;
    acc.x = self.x * dself;
    acc.y = self.y * dself;
    acc.z = self.z * dself;
    acc.w = self.w * dself;

    int k = s;
    for (; k + 4 <= e; k += 4) {
        int s0 = g_srcidx[k + 0];
        int s1 = g_srcidx[k + 1];
        int s2 = g_srcidx[k + 2];
        int s3 = g_srcidx[k + 3];
        float d0 = g_dinv[s0], d1 = g_dinv[s1], d2 = g_dinv[s2], d3 = g_dinv[s3];
        float4 v0 = *reinterpret_cast<const float4*>(&hs[(size_t)s0 * C1 + lane * 4]);
        float4 v1 = *reinterpret_cast<const float4*>(&hs[(size_t)s1 * C1 + lane * 4]);
        float4 v2 = *reinterpret_cast<const float4*>(&hs[(size_t)s2 * C1 + lane * 4]);
        float4 v3 = *reinterpret_cast<const float4*>(&hs[(size_t)s3 * C1 + lane * 4]);
        acc.x += v0.x * d0 + v1.x * d1 + v2.x * d2 + v3.x * d3;
        acc.y += v0.y * d0 + v1.y * d1 + v2.y * d2 + v3.y * d3;
        acc.z += v0.z * d0 + v1.z * d1 + v2.z * d2 + v3.z * d3;
        acc.w += v0.w * d0 + v1.w * d1 + v2.w * d2 + v3.w * d3;
    }
    for (; k < e; k++) {
        int sk = g_srcidx[k];
        float dk = g_dinv[sk];
        float4 v = *reinterpret_cast<const float4*>(&hs[(size_t)sk * C1 + lane * 4]);
        acc.x += v.x * dk; acc.y += v.y * dk; acc.z += v.z * dk; acc.w += v.w * dk;
    }

    float4 b = *reinterpret_cast<const float4*>(&bias[lane * 4]);
    float4 o;
    o.x = fmaxf(dself * acc.x + b.x, 0.f);
    o.y = fmaxf(dself * acc.y + b.y, 0.f);
    o.z = fmaxf(dself * acc.z + b.z, 0.f);
    o.w = fmaxf(dself * acc.w + b.w, 0.f);

    ushort4 hv, lv;
    split_bf16(o.x, hv.x, lv.x);
    split_bf16(o.y, hv.y, lv.y);
    split_bf16(o.z, hv.z, lv.z);
    split_bf16(o.w, hv.w, lv.w);
    hrow[lane] = hv;
    lrow[lane] = lv;
}

// C=64: one warp per node, float2 per lane, fp32 output
__global__ void gather64_kernel(const float* __restrict__ hs, float* __restrict__ out,
                                const float* __restrict__ bias) {
    int gw   = (blockIdx.x * blockDim.x + threadIdx.x) >> 5;
    int lane = threadIdx.x & 31;
    if (gw >= N_NODES) return;
    const int s = g_off[gw];
    const int e = g_off[gw + 1];
    const float dself = g_dinv[gw];

    float2 self = *reinterpret_cast<const float2*>(&hs[(size_t)gw * C2 + lane * 2]);
    float2 acc;
    acc.x = self.x * dself;
    acc.y = self.y * dself;

    int k = s;
    for (; k + 4 <= e; k += 4) {
        int s0 = g_srcidx[k + 0];
        int s1 = g_srcidx[k + 1];
        int s2 = g_srcidx[k + 2];
        int s3 = g_srcidx[k + 3];
        float d0 = g_dinv[s0], d1 = g_dinv[s1], d2 = g_dinv[s2], d3 = g_dinv[s3];
        float2 v0 = *reinterpret_cast<const float2*>(&hs[(size_t)s0 * C2 + lane * 2]);
        float2 v1 = *reinterpret_cast<const float2*>(&hs[(size_t)s1 * C2 + lane * 2]);
        float2 v2 = *reinterpret_cast<const float2*>(&hs[(size_t)s2 * C2 + lane * 2]);
        float2 v3 = *reinterpret_cast<const float2*>(&hs[(size_t)s3 * C2 + lane * 2]);
        acc.x += v0.x * d0 + v1.x * d1 + v2.x * d2 + v3.x * d3;
        acc.y += v0.y * d0 + v1.y * d1 + v2.y * d2 + v3.y * d3;
    }
    for (; k < e; k++) {
        int sk = g_srcidx[k];
        float dk = g_dinv[sk];
        float2 v = *reinterpret_cast<const float2*>(&hs[(size_t)sk * C2 + lane * 2]);
        acc.x += v.x * dk; acc.y += v.y * dk;
    }

    float2 b = *reinterpret_cast<const float2*>(&bias[lane * 2]);
    float2 o;
    o.x = dself * acc.x + b.x;
    o.y = dself * acc.y + b.y;
    *reinterpret_cast<float2*>(&out[(size_t)gw * C2 + lane * 2]) = o;
}

// ---------------- logits ----------------
__global__ void logits_kernel(int Q, const float* __restrict__ z, float* __restrict__ out) {
    long long idx = (long long)blockIdx.x * blockDim.x + threadIdx.x;
    long long e = idx / 16;
    int j       = (int)(idx % 16);
    if (e >= Q) return;
    int a = g_qa[e];
    int b = g_qb[e];
    float4 va = *reinterpret_cast<const float4*>(&z[(size_t)a * C2 + j * 4]);
    float4 vb = *reinterpret_cast<const float4*>(&z[(size_t)b * C2 + j * 4]);
    float d = va.x * vb.x + va.y * vb.y + va.z * vb.z + va.w * vb.w;
#pragma unroll
    for (int off = 8; off > 0; off >>= 1)
        d += __shfl_xor_sync(0xffffffffu, d, off, 16);
    if (j == 0) out[e] = d;
}

// ---------------- launch ----------------
extern "C" void kernel_launch(void* const* d_in, const int* in_sizes, int n_in,
                              void* d_out, int out_size) {
    const float* x   = (const float*)d_in[0];
    const void*  ei  = d_in[1];
    const void*  pos = d_in[2];
    const void*  neg = d_in[3];
    const float* W1  = (const float*)d_in[4];
    const float* b1  = (const float*)d_in[5];
    const float* W2  = (const float*)d_in[6];
    const float* b2  = (const float*)d_in[7];
    float* out = (float*)d_out;

    const int E  = in_sizes[1] / 2;
    const int Ep = in_sizes[2] / 2;
    const int En = in_sizes[3] / 2;
    const int Q  = Ep + En;

    float *hs1, *hs2, *z;
    __nv_bfloat16 *xhi, *xlo, *w1thi, *w1tlo, *hhi, *hlo, *w2thi, *w2tlo;
    cudaGetSymbolAddress((void**)&hs1,   g_hs1);
    cudaGetSymbolAddress((void**)&hs2,   g_hs2);
    cudaGetSymbolAddress((void**)&z,     g_z);
    cudaGetSymbolAddress((void**)&xhi,   g_xhi);
    cudaGetSymbolAddress((void**)&xlo,   g_xlo);
    cudaGetSymbolAddress((void**)&w1thi, g_w1thi);
    cudaGetSymbolAddress((void**)&w1tlo, g_w1tlo);
    cudaGetSymbolAddress((void**)&hhi,   g_hhi);
    cudaGetSymbolAddress((void**)&hlo,   g_hlo);
    cudaGetSymbolAddress((void**)&w2thi, g_w2thi);
    cudaGetSymbolAddress((void**)&w2tlo, g_w2tlo);

    // double-buffered stages: 2 * (A hi+lo + B hi+lo)
    constexpr int SMEM1 = 2 * (2 * (128 * 128) + 2 * (C1 * 128));  // 131072
    constexpr int SMEM2 = 2 * (2 * (128 * 128) + 2 * (C2 * 128));  // 98304
    cudaFuncSetAttribute(mma_gemm_kernel<C1, CIN>, cudaFuncAttributeMaxDynamicSharedMemorySize, SMEM1);
    cudaFuncSetAttribute(mma_gemm_kernel<C2, C1>,  cudaFuncAttributeMaxDynamicSharedMemorySize, SMEM2);

    const int NTILES = NPAD / 128;   // 391

    // launch order (GEMM1 at index 3 = the ncu-profiled slot)
    {
        size_t n = (size_t)NPAD * CIN / 4;
        split_x_kernel<<<(int)((n + 255) / 256), 256>>>(x);                        // 0
    }
    split_wt_kernel<CIN, C1><<<(CIN * C1 + 255) / 256, 256>>>(W1, w1thi, w1tlo);   // 1
    detect_kernel<<<1, 32>>>((const int*)ei);                                       // 2
    mma_gemm_kernel<C1, CIN><<<NTILES, 256, SMEM1>>>(xhi, xlo, w1thi, w1tlo, hs1); // 3
    zero_deg_kernel<<<(N_NODES + 255) / 256, 256>>>();                              // 4
    convert_edges_kernel<<<(E + 255) / 256, 256>>>(ei, E);                          // 5
    convert_queries_kernel<<<(Q + 255) / 256, 256>>>(pos, neg, Ep, En);             // 6
    dinv_kernel<<<(N_NODES + 255) / 256, 256>>>();                                  // 7
    scan_kernel<<<1, 1024>>>();                                                     // 8
    fill_kernel<<<(E + 255) / 256, 256>>>(E);                                       // 9
    split_wt_kernel<C1, C2><<<(C1 * C2 + 255) / 256, 256>>>(W2, w2thi, w2tlo);      // 10
    gather128_kernel<<<(NPAD * 32 + 255) / 256, 256>>>(hs1, b1);                    // 11
    mma_gemm_kernel<C2, C1><<<NTILES, 256, SMEM2>>>(hhi, hlo, w2thi, w2tlo, hs2);   // 12
    gather64_kernel<<<(N_NODES * 32 + 255) / 256, 256>>>(hs2, z, b2);               // 13
    {
        long long tot = (long long)Q * 16;
        logits_kernel<<<(int)((tot + 255) / 256), 256>>>(Q, z, out);                // 14
    }
}

// round 15
// speedup vs baseline: 1.8436x; 1.0133x over previous
#include <cuda_runtime.h>
#include <cuda_bf16.h>
#include <cstdint>

// ---------------- problem constants ----------------
#define N_NODES 50000
#define E_MAX   800000
#define Q_MAX   400000
constexpr int CIN  = 256;   // input channels
constexpr int C1   = 128;   // hidden channels
constexpr int C2   = 64;    // output channels
constexpr int NPAD = 50048; // 391 * 128 (padded rows for 128-row GEMM tiles)

// ---------------- device scratch (static; no allocs allowed) ----------------
__device__ int g_is64;
__device__ __align__(16) int   g_src   [E_MAX];
__device__ __align__(16) int   g_dst   [E_MAX];
__device__ __align__(16) int   g_qa    [Q_MAX];
__device__ __align__(16) int   g_qb    [Q_MAX];
__device__ __align__(16) int   g_deg   [N_NODES];
__device__ __align__(16) int   g_off   [N_NODES + 1];
__device__ __align__(16) int   g_cur   [N_NODES];
__device__ __align__(16) int   g_srcidx[E_MAX];
__device__ __align__(16) float g_dinv  [N_NODES];
// bf16 hi/lo split operands for tensor-core GEMMs
__device__ __align__(16) __nv_bfloat16 g_xhi [(size_t)NPAD * CIN];
__device__ __align__(16) __nv_bfloat16 g_xlo [(size_t)NPAD * CIN];
__device__ __align__(16) __nv_bfloat16 g_w1thi[(size_t)C1 * CIN];   // W1^T [C1][CIN]
__device__ __align__(16) __nv_bfloat16 g_w1tlo[(size_t)C1 * CIN];
__device__ __align__(16) __nv_bfloat16 g_hhi [(size_t)NPAD * C1];   // relu(h) split
__device__ __align__(16) __nv_bfloat16 g_hlo [(size_t)NPAD * C1];
__device__ __align__(16) __nv_bfloat16 g_w2thi[(size_t)C2 * C1];    // W2^T [C2][C1]
__device__ __align__(16) __nv_bfloat16 g_w2tlo[(size_t)C2 * C1];
// fp32 intermediates
__device__ __align__(16) float g_hs1[(size_t)NPAD * C1];   // x @ W1
__device__ __align__(16) float g_hs2[(size_t)NPAD * C2];   // h @ W2
__device__ __align__(16) float g_z  [(size_t)N_NODES * C2];

// ---------------- helpers ----------------
__device__ __forceinline__ uint32_t smem_u32(const void* p) {
    uint32_t a;
    asm("{ .reg .u64 t; cvta.to.shared.u64 t, %1; cvt.u32.u64 %0, t; }" : "=r"(a) : "l"(p));
    return a;
}
__device__ __forceinline__ uint32_t sw128(uint32_t off) { return off ^ ((off >> 3) & 0x70); }

__device__ __forceinline__ void ldsm_x4(uint32_t* r, uint32_t addr) {
    asm volatile("ldmatrix.sync.aligned.m8n8.x4.shared.b16 {%0,%1,%2,%3}, [%4];"
                 : "=r"(r[0]), "=r"(r[1]), "=r"(r[2]), "=r"(r[3]) : "r"(addr));
}
// D += A * B  (m16n8k16, bf16 inputs, fp32 accum)
__device__ __forceinline__ void mma_bf16(float* d, const uint32_t* a, const uint32_t* b) {
    asm volatile("mma.sync.aligned.m16n8k16.row.col.f32.bf16.bf16.f32 "
                 "{%0,%1,%2,%3}, {%4,%5,%6,%7}, {%8,%9}, {%0,%1,%2,%3};"
                 : "+f"(d[0]), "+f"(d[1]), "+f"(d[2]), "+f"(d[3])
                 : "r"(a[0]), "r"(a[1]), "r"(a[2]), "r"(a[3]), "r"(b[0]), "r"(b[1]));
}
// async 16B copy global -> shared (sm_80 baseline)
#define CP_ASYNC16(dst_u32, src_ptr) \
    asm volatile("cp.async.cg.shared.global [%0], [%1], 16;" :: "r"(dst_u32), "l"(src_ptr))
#define CP_COMMIT() asm volatile("cp.async.commit_group;" ::: "memory")
#define CP_WAIT(n)  asm volatile("cp.async.wait_group %0;" :: "n"(n) : "memory")

__device__ __forceinline__ void split_bf16(float v, unsigned short& h, unsigned short& l) {
    __nv_bfloat16 bh = __float2bfloat16(v);
    __nv_bfloat16 bl = __float2bfloat16(v - __bfloat162float(bh));
    h = __bfloat16_as_ushort(bh);
    l = __bfloat16_as_ushort(bl);
}
__device__ __forceinline__ int clamp_idx(long long v) {
    if (v < 0) v = 0;
    if (v >= N_NODES) v = N_NODES - 1;
    return (int)v;
}

// ================= fused prep =================
// blockIdx ranges: [0,NXB) split_x | [NXB,+128) split_wt1 | [+32) split_wt2
//                  | [+ZB) zero_deg | last block: detect
constexpr int NXB  = (int)((size_t)NPAD * CIN / 4 / 256);  // 12512 (exact)
constexpr int WT1B = CIN * C1 / 256;                        // 128 (exact)
constexpr int WT2B = C1 * C2 / 256;                         // 32 (exact)
constexpr int ZB   = (N_NODES + 255) / 256;                 // 196
constexpr int PREP_BLOCKS = NXB + WT1B + WT2B + ZB + 1;

__global__ void prep_kernel(const float* __restrict__ x,
                            const float* __restrict__ W1, const float* __restrict__ W2,
                            const int* __restrict__ ei32) {
    const int b   = blockIdx.x;
    const int tid = threadIdx.x;
    if (b < NXB) {
        // split_x: fp32 -> bf16 hi/lo, pad rows zero
        size_t i   = (size_t)b * 256 + tid;
        size_t row = i / (CIN / 4);
        float4 v = make_float4(0.f, 0.f, 0.f, 0.f);
        if (row < N_NODES) v = reinterpret_cast<const float4*>(x)[i];
        ushort4 h, l;
        split_bf16(v.x, h.x, l.x);
        split_bf16(v.y, h.y, l.y);
        split_bf16(v.z, h.z, l.z);
        split_bf16(v.w, h.w, l.w);
        reinterpret_cast<ushort4*>(g_xhi)[i] = h;
        reinterpret_cast<ushort4*>(g_xlo)[i] = l;
    } else if (b < NXB + WT1B) {
        // split_wt1: W1 [CIN, C1] -> W1t hi/lo [C1, CIN]
        int i = (b - NXB) * 256 + tid;
        int n = i / CIN, k = i % CIN;
        unsigned short h, l;
        split_bf16(W1[(size_t)k * C1 + n], h, l);
        g_w1thi[(size_t)n * CIN + k] = __ushort_as_bfloat16(h);
        g_w1tlo[(size_t)n * CIN + k] = __ushort_as_bfloat16(l);
    } else if (b < NXB + WT1B + WT2B) {
        // split_wt2: W2 [C1, C2] -> W2t hi/lo [C2, C1]
        int i = (b - NXB - WT1B) * 256 + tid;
        int n = i / C1, k = i % C1;
        unsigned short h, l;
        split_bf16(W2[(size_t)k * C2 + n], h, l);
        g_w2thi[(size_t)n * C1 + k] = __ushort_as_bfloat16(h);
        g_w2tlo[(size_t)n * C1 + k] = __ushort_as_bfloat16(l);
    } else if (b < NXB + WT1B + WT2B + ZB) {
        int i = (b - NXB - WT1B - WT2B) * 256 + tid;
        if (i < N_NODES) g_deg[i] = 0;
    } else {
        // detect: int64 buffers have all-zero high words
        if (tid < 32) {
            int v = ei32[2 * tid + 1];
            unsigned nz = __ballot_sync(0xffffffffu, v != 0);
            if (tid == 0) g_is64 = (nz == 0u) ? 1 : 0;
        }
    }
}

// ================= fused converts: edges + queries =================
__global__ void converts_kernel(const void* __restrict__ ei,
                                const void* __restrict__ pos, const void* __restrict__ neg,
                                int E, int Ep, int En, int EB) {
    const int b   = blockIdx.x;
    const int tid = threadIdx.x;
    const int is64 = g_is64;
    if (b < EB) {
        int e = b * 256 + tid;
        if (e >= E) return;
        int s, d;
        if (is64) {
            const long long* p = (const long long*)ei;
            s = clamp_idx(p[e]);
            d = clamp_idx(p[E + e]);
        } else {
            const int* p = (const int*)ei;
            s = clamp_idx(p[e]);
            d = clamp_idx(p[E + e]);
        }
        g_src[e] = s;
        g_dst[e] = d;
        atomicAdd(&g_deg[d], 1);
    } else {
        int i = (b - EB) * 256 + tid;
        if (i >= Ep + En) return;
        int a, bb;
        if (is64) {
            if (i < Ep) {
                const long long* p = (const long long*)pos;
                a  = clamp_idx(p[i]);
                bb = clamp_idx(p[Ep + i]);
            } else {
                const long long* p = (const long long*)neg;
                a  = clamp_idx(p[i - Ep]);
                bb = clamp_idx(p[En + i - Ep]);
            }
        } else {
            if (i < Ep) {
                const int* p = (const int*)pos;
                a  = clamp_idx(p[i]);
                bb = clamp_idx(p[Ep + i]);
            } else {
                const int* p = (const int*)neg;
                a  = clamp_idx(p[i - Ep]);
                bb = clamp_idx(p[En + i - Ep]);
            }
        }
        g_qa[i] = a;
        g_qb[i] = bb;
    }
}

// ================= scan (+ fused dinv) =================
__global__ void __launch_bounds__(1024) scan_dinv_kernel() {
    __shared__ int wsum[32];
    __shared__ int s_carry;
    const int tid  = threadIdx.x;
    const int lane = tid & 31;
    const int wid  = tid >> 5;
    if (tid == 0) s_carry = 0;
    __syncthreads();
    for (int base = 0; base < N_NODES; base += 1024) {
        int i = base + tid;
        int v = (i < N_NODES) ? g_deg[i] : 0;
        int inc = v;
#pragma unroll
        for (int o = 1; o < 32; o <<= 1) {
            int t = __shfl_up_sync(0xffffffffu, inc, o);
            if (lane >= o) inc += t;
        }
        if (lane == 31) wsum[wid] = inc;
        __syncthreads();
        if (wid == 0) {
            int w = wsum[lane];
            int winc = w;
#pragma unroll
            for (int o = 1; o < 32; o <<= 1) {
                int t = __shfl_up_sync(0xffffffffu, winc, o);
                if (lane >= o) winc += t;
            }
            wsum[lane] = winc;
        }
        __syncthreads();
        int excl = s_carry + ((wid > 0) ? wsum[wid - 1] : 0) + inc - v;
        if (i < N_NODES) {
            g_off[i]  = excl;
            g_cur[i]  = excl;
            g_dinv[i] = rsqrtf((float)(v + 1));   // +1 self-loop
        }
        int chunk_total = wsum[31];
        __syncthreads();
        if (tid == 0) s_carry += chunk_total;
        __syncthreads();
    }
    if (threadIdx.x == 0) g_off[N_NODES] = s_carry;
}

__global__ void fill_kernel(int E) {
    int e = blockIdx.x * blockDim.x + threadIdx.x;
    if (e < E) {
        int pos = atomicAdd(&g_cur[g_dst[e]], 1);
        g_srcidx[pos] = g_src[e];
    }
}

// ================= HMMA GEMM (cp.async double-buffered; R14-proven) =================
template <int N_DIM, int K_DIM>
__global__ void __launch_bounds__(256)
mma_gemm_kernel(const __nv_bfloat16* __restrict__ a_hi, const __nv_bfloat16* __restrict__ a_lo,
                const __nv_bfloat16* __restrict__ b_hi, const __nv_bfloat16* __restrict__ b_lo,
                float* __restrict__ out) {
    constexpr int NCHUNK = K_DIM / 64;
    constexpr int NT     = N_DIM / 8;
    constexpr int A_TILE = 128 * 128;
    constexpr int B_TILE = N_DIM * 128;
    constexpr int S_A_HI = 0;
    constexpr int S_A_LO = A_TILE;
    constexpr int S_B_HI = 2 * A_TILE;
    constexpr int S_B_LO = 2 * A_TILE + B_TILE;
    constexpr int STAGE  = 2 * A_TILE + 2 * B_TILE;

    extern __shared__ char smem[];
    const uint32_t sbase = smem_u32(smem);
    const int tid  = threadIdx.x;
    const int wid  = tid >> 5;
    const int lane = tid & 31;
    const int row0 = blockIdx.x * 128;

    float acc[NT][4];
#pragma unroll
    for (int t = 0; t < NT; t++)
#pragma unroll
        for (int c = 0; c < 4; c++) acc[t][c] = 0.f;

    const int g = lane >> 3, l8 = lane & 7;
    const int a_row = wid * 16 + l8 + ((g & 1) ? 8 : 0);
    const int a_k8  = (g >> 1) ? 8 : 0;
    const int b_nrel = l8 + ((g >> 1) ? 8 : 0);
    const int b_k8   = (g & 1) ? 8 : 0;

    constexpr int KU4 = K_DIM / 8;

    auto stage = [&](int kc, int buf) {
        const uint32_t SB = sbase + buf * STAGE;
#pragma unroll
        for (int li = 0; li < 4; li++) {
            int f = tid + li * 256;
            int r = f >> 3, c16 = f & 7;
            uint32_t sw = sw128((uint32_t)(r * 128 + c16 * 16));
            size_t gi = (size_t)(row0 + r) * KU4 + (size_t)kc * 8 + c16;
            CP_ASYNC16(SB + S_A_HI + sw, reinterpret_cast<const uint4*>(a_hi) + gi);
            CP_ASYNC16(SB + S_A_LO + sw, reinterpret_cast<const uint4*>(a_lo) + gi);
        }
#pragma unroll
        for (int f = tid; f < N_DIM * 8; f += 256) {
            int n = f >> 3, c16 = f & 7;
            uint32_t sw = sw128((uint32_t)(n * 128 + c16 * 16));
            size_t gi = (size_t)n * KU4 + (size_t)kc * 8 + c16;
            CP_ASYNC16(SB + S_B_HI + sw, reinterpret_cast<const uint4*>(b_hi) + gi);
            CP_ASYNC16(SB + S_B_LO + sw, reinterpret_cast<const uint4*>(b_lo) + gi);
        }
        CP_COMMIT();
    };

    stage(0, 0);

    for (int kc = 0; kc < NCHUNK; kc++) {
        const int buf = kc & 1;
        if (kc > 0) __syncthreads();
        if (kc + 1 < NCHUNK) {
            stage(kc + 1, buf ^ 1);
            CP_WAIT(1);
        } else {
            CP_WAIT(0);
        }
        __syncthreads();

        const uint32_t SB = sbase + buf * STAGE;
#pragma unroll
        for (int ks = 0; ks < 4; ks++) {
            uint32_t ah[4], al[4];
            uint32_t a_off = sw128((uint32_t)(a_row * 128 + (ks * 16 + a_k8) * 2));
            ldsm_x4(ah, SB + S_A_HI + a_off);
            ldsm_x4(al, SB + S_A_LO + a_off);
#pragma unroll
            for (int np = 0; np < NT / 2; np++) {
                uint32_t bh[4], bl[4];
                uint32_t b_off = sw128((uint32_t)((np * 16 + b_nrel) * 128 + (ks * 16 + b_k8) * 2));
                ldsm_x4(bh, SB + S_B_HI + b_off);
                ldsm_x4(bl, SB + S_B_LO + b_off);
                mma_bf16(acc[2 * np],     ah, bh);
                mma_bf16(acc[2 * np + 1], ah, bh + 2);
                mma_bf16(acc[2 * np],     ah, bl);
                mma_bf16(acc[2 * np + 1], ah, bl + 2);
                mma_bf16(acc[2 * np],     al, bh);
                mma_bf16(acc[2 * np + 1], al, bh + 2);
            }
        }
    }

    const size_t rlo  = (size_t)row0 + wid * 16 + (lane >> 2);
    const int    col0 = (lane & 3) * 2;
#pragma unroll
    for (int nt = 0; nt < NT; nt++) {
        float2 v0 = make_float2(acc[nt][0], acc[nt][1]);
        float2 v1 = make_float2(acc[nt][2], acc[nt][3]);
        *reinterpret_cast<float2*>(&out[rlo * N_DIM + nt * 8 + col0])       = v0;
        *reinterpret_cast<float2*>(&out[(rlo + 8) * N_DIM + nt * 8 + col0]) = v1;
    }
}

// ================= gather + combine (R14-proven) =================
__global__ void gather128_kernel(const float* __restrict__ hs,
                                 const float* __restrict__ bias) {
    int gw   = (blockIdx.x * blockDim.x + threadIdx.x) >> 5;
    int lane = threadIdx.x & 31;
    if (gw >= NPAD) return;
    ushort4* hrow = reinterpret_cast<ushort4*>(g_hhi + (size_t)gw * C1);
    ushort4* lrow = reinterpret_cast<ushort4*>(g_hlo + (size_t)gw * C1);
    if (gw >= N_NODES) {
        ushort4 zz = make_ushort4(0, 0, 0, 0);
        hrow[lane] = zz;
        lrow[lane] = zz;
        return;
    }
    const int s = g_off[gw];
    const int e = g_off[gw + 1];
    const float dself = g_dinv[gw];

    float4 self = *reinterpret_cast<const float4*>(&hs[(size_t)gw * C1 + lane * 4]);
    float4 acc;
    acc.x = self.x * dself;
    acc.y = self.y * dself;
    acc.z = self.z * dself;
    acc.w = self.w * dself;

    int k = s;
    for (; k + 4 <= e; k += 4) {
        int s0 = g_srcidx[k + 0];
        int s1 = g_srcidx[k + 1];
        int s2 = g_srcidx[k + 2];
        int s3 = g_srcidx[k + 3];
        float d0 = g_dinv[s0], d1 = g_dinv[s1], d2 = g_dinv[s2], d3 = g_dinv[s3];
        float4 v0 = *reinterpret_cast<const float4*>(&hs[(size_t)s0 * C1 + lane * 4]);
        float4 v1 = *reinterpret_cast<const float4*>(&hs[(size_t)s1 * C1 + lane * 4]);
        float4 v2 = *reinterpret_cast<const float4*>(&hs[(size_t)s2 * C1 + lane * 4]);
        float4 v3 = *reinterpret_cast<const float4*>(&hs[(size_t)s3 * C1 + lane * 4]);
        acc.x += v0.x * d0 + v1.x * d1 + v2.x * d2 + v3.x * d3;
        acc.y += v0.y * d0 + v1.y * d1 + v2.y * d2 + v3.y * d3;
        acc.z += v0.z * d0 + v1.z * d1 + v2.z * d2 + v3.z * d3;
        acc.w += v0.w * d0 + v1.w * d1 + v2.w * d2 + v3.w * d3;
    }
    for (; k < e; k++) {
        int sk = g_srcidx[k];
        float dk = g_dinv[sk];
        float4 v = *reinterpret_cast<const float4*>(&hs[(size_t)sk * C1 + lane * 4]);
        acc.x += v.x * dk; acc.y += v.y * dk; acc.z += v.z * dk; acc.w += v.w * dk;
    }

    float4 b = *reinterpret_cast<const float4*>(&bias[lane * 4]);
    float4 o;
    o.x = fmaxf(dself * acc.x + b.x, 0.f);
    o.y = fmaxf(dself * acc.y + b.y, 0.f);
    o.z = fmaxf(dself * acc.z + b.z, 0.f);
    o.w = fmaxf(dself * acc.w + b.w, 0.f);

    ushort4 hv, lv;
    split_bf16(o.x, hv.x, lv.x);
    split_bf16(o.y, hv.y, lv.y);
    split_bf16(o.z, hv.z, lv.z);
    split_bf16(o.w, hv.w, lv.w);
    hrow[lane] = hv;
    lrow[lane] = lv;
}

__global__ void gather64_kernel(const float* __restrict__ hs, float* __restrict__ out,
                                const float* __restrict__ bias) {
    int gw   = (blockIdx.x * blockDim.x + threadIdx.x) >> 5;
    int lane = threadIdx.x & 31;
    if (gw >= N_NODES) return;
    const int s = g_off[gw];
    const int e = g_off[gw + 1];
    const float dself = g_dinv[gw];

    float2 self = *reinterpret_cast<const float2*>(&hs[(size_t)gw * C2 + lane * 2]);
    float2 acc;
    acc.x = self.x * dself;
    acc.y = self.y * dself;

    int k = s;
    for (; k + 4 <= e; k += 4) {
        int s0 = g_srcidx[k + 0];
        int s1 = g_srcidx[k + 1];
        int s2 = g_srcidx[k + 2];
        int s3 = g_srcidx[k + 3];
        float d0 = g_dinv[s0], d1 = g_dinv[s1], d2 = g_dinv[s2], d3 = g_dinv[s3];
        float2 v0 = *reinterpret_cast<const float2*>(&hs[(size_t)s0 * C2 + lane * 2]);
        float2 v1 = *reinterpret_cast<const float2*>(&hs[(size_t)s1 * C2 + lane * 2]);
        float2 v2 = *reinterpret_cast<const float2*>(&hs[(size_t)s2 * C2 + lane * 2]);
        float2 v3 = *reinterpret_cast<const float2*>(&hs[(size_t)s3 * C2 + lane * 2]);
        acc.x += v0.x * d0 + v1.x * d1 + v2.x * d2 + v3.x * d3;
        acc.y += v0.y * d0 + v1.y * d1 + v2.y * d2 + v3.y * d3;
    }
    for (; k < e; k++) {
        int sk = g_srcidx[k];
        float dk = g_dinv[sk];
        float2 v = *reinterpret_cast<const float2*>(&hs[(size_t)sk * C2 + lane * 2]);
        acc.x += v.x * dk; acc.y += v.y * dk;
    }

    float2 b = *reinterpret_cast<const float2*>(&bias[lane * 2]);
    float2 o;
    o.x = dself * acc.x + b.x;
    o.y = dself * acc.y + b.y;
    *reinterpret_cast<float2*>(&out[(size_t)gw * C2 + lane * 2]) = o;
}

// ---------------- logits ----------------
__global__ void logits_kernel(int Q, const float* __restrict__ z, float* __restrict__ out) {
    long long idx = (long long)blockIdx.x * blockDim.x + threadIdx.x;
    long long e = idx / 16;
    int j       = (int)(idx % 16);
    if (e >= Q) return;
    int a = g_qa[e];
    int b = g_qb[e];
    float4 va = *reinterpret_cast<const float4*>(&z[(size_t)a * C2 + j * 4]);
    float4 vb = *reinterpret_cast<const float4*>(&z[(size_t)b * C2 + j * 4]);
    float d = va.x * vb.x + va.y * vb.y + va.z * vb.z + va.w * vb.w;
#pragma unroll
    for (int off = 8; off > 0; off >>= 1)
        d += __shfl_xor_sync(0xffffffffu, d, off, 16);
    if (j == 0) out[e] = d;
}

// ---------------- launch ----------------
extern "C" void kernel_launch(void* const* d_in, const int* in_sizes, int n_in,
                              void* d_out, int out_size) {
    const float* x   = (const float*)d_in[0];
    const void*  ei  = d_in[1];
    const void*  pos = d_in[2];
    const void*  neg = d_in[3];
    const float* W1  = (const float*)d_in[4];
    const float* b1  = (const float*)d_in[5];
    const float* W2  = (const float*)d_in[6];
    const float* b2  = (const float*)d_in[7];
    float* out = (float*)d_out;

    const int E  = in_sizes[1] / 2;
    const int Ep = in_sizes[2] / 2;
    const int En = in_sizes[3] / 2;
    const int Q  = Ep + En;

    float *hs1, *hs2, *z;
    __nv_bfloat16 *xhi, *xlo, *w1thi, *w1tlo, *hhi, *hlo, *w2thi, *w2tlo;
    cudaGetSymbolAddress((void**)&hs1,   g_hs1);
    cudaGetSymbolAddress((void**)&hs2,   g_hs2);
    cudaGetSymbolAddress((void**)&z,     g_z);
    cudaGetSymbolAddress((void**)&xhi,   g_xhi);
    cudaGetSymbolAddress((void**)&xlo,   g_xlo);
    cudaGetSymbolAddress((void**)&w1thi, g_w1thi);
    cudaGetSymbolAddress((void**)&w1tlo, g_w1tlo);
    cudaGetSymbolAddress((void**)&hhi,   g_hhi);
    cudaGetSymbolAddress((void**)&hlo,   g_hlo);
    cudaGetSymbolAddress((void**)&w2thi, g_w2thi);
    cudaGetSymbolAddress((void**)&w2tlo, g_w2tlo);

    constexpr int SMEM1 = 2 * (2 * (128 * 128) + 2 * (C1 * 128));  // 131072
    constexpr int SMEM2 = 2 * (2 * (128 * 128) + 2 * (C2 * 128));  // 98304
    cudaFuncSetAttribute(mma_gemm_kernel<C1, CIN>, cudaFuncAttributeMaxDynamicSharedMemorySize, SMEM1);
    cudaFuncSetAttribute(mma_gemm_kernel<C2, C1>,  cudaFuncAttributeMaxDynamicSharedMemorySize, SMEM2);

    const int NTILES = NPAD / 128;        // 391
    const int EB = (E + 255) / 256;       // 3125
    const int QB = (Q + 255) / 256;       // 1563

    prep_kernel<<<PREP_BLOCKS, 256>>>(x, W1, W2, (const int*)ei);                    // 0
    converts_kernel<<<EB + QB, 256>>>(ei, pos, neg, E, Ep, En, EB);                  // 1
    scan_dinv_kernel<<<1, 1024>>>();                                                  // 2
    mma_gemm_kernel<C1, CIN><<<NTILES, 256, SMEM1>>>(xhi, xlo, w1thi, w1tlo, hs1);   // 3 (profiled slot)
    fill_kernel<<<EB, 256>>>(E);                                                      // 4
    gather128_kernel<<<(NPAD * 32 + 255) / 256, 256>>>(hs1, b1);                      // 5
    mma_gemm_kernel<C2, C1><<<NTILES, 256, SMEM2>>>(hhi, hlo, w2thi, w2tlo, hs2);    // 6
    gather64_kernel<<<(N_NODES * 32 + 255) / 256, 256>>>(hs2, z, b2);                 // 7
    {
        long long tot = (long long)Q * 16;
        logits_kernel<<<(int)((tot + 255) / 256), 256>>>(Q, z, out);                  // 8
    }
}

// round 16
// speedup vs baseline: 1.9792x; 1.0735x over previous
#include <cuda_runtime.h>
#include <cuda_bf16.h>
#include <cstdint>

// ---------------- problem constants ----------------
#define N_NODES 50000
#define E_MAX   800000
#define Q_MAX   400000
constexpr int CIN  = 256;   // input channels
constexpr int C1   = 128;   // hidden channels
constexpr int C2   = 64;    // output channels
constexpr int NPAD = 50048; // 391 * 128 (padded rows for 128-row GEMM tiles)

// ---------------- device scratch (static; no allocs allowed) ----------------
__device__ int g_is64;
__device__ __align__(16) int   g_src   [E_MAX];
__device__ __align__(16) int   g_dst   [E_MAX];
__device__ __align__(16) int   g_qa    [Q_MAX];
__device__ __align__(16) int   g_qb    [Q_MAX];
__device__ __align__(16) int   g_deg   [N_NODES];
__device__ __align__(16) int   g_off   [N_NODES + 1];
__device__ __align__(16) int   g_cur   [N_NODES];
__device__ __align__(16) int   g_srcidx[E_MAX];
__device__ __align__(16) float g_dinv  [N_NODES];
// bf16 hi/lo split operands for tensor-core GEMMs
__device__ __align__(16) __nv_bfloat16 g_xhi [(size_t)NPAD * CIN];
__device__ __align__(16) __nv_bfloat16 g_xlo [(size_t)NPAD * CIN];
__device__ __align__(16) __nv_bfloat16 g_w1thi[(size_t)C1 * CIN];   // W1^T [C1][CIN]
__device__ __align__(16) __nv_bfloat16 g_w1tlo[(size_t)C1 * CIN];
__device__ __align__(16) __nv_bfloat16 g_hhi [(size_t)NPAD * C1];   // relu(h) split
__device__ __align__(16) __nv_bfloat16 g_hlo [(size_t)NPAD * C1];
__device__ __align__(16) __nv_bfloat16 g_w2thi[(size_t)C2 * C1];    // W2^T [C2][C1]
__device__ __align__(16) __nv_bfloat16 g_w2tlo[(size_t)C2 * C1];
// fp32 intermediates
__device__ __align__(16) float g_hs1[(size_t)NPAD * C1];   // x @ W1
__device__ __align__(16) float g_hs2[(size_t)NPAD * C2];   // h @ W2
__device__ __align__(16) float g_z  [(size_t)N_NODES * C2];

// ---------------- helpers ----------------
__device__ __forceinline__ uint32_t smem_u32(const void* p) {
    uint32_t a;
    asm("{ .reg .u64 t; cvta.to.shared.u64 t, %1; cvt.u32.u64 %0, t; }" : "=r"(a) : "l"(p));
    return a;
}
__device__ __forceinline__ uint32_t sw128(uint32_t off) { return off ^ ((off >> 3) & 0x70); }

__device__ __forceinline__ void ldsm_x4(uint32_t* r, uint32_t addr) {
    asm volatile("ldmatrix.sync.aligned.m8n8.x4.shared.b16 {%0,%1,%2,%3}, [%4];"
                 : "=r"(r[0]), "=r"(r[1]), "=r"(r[2]), "=r"(r[3]) : "r"(addr));
}
// D += A * B  (m16n8k16, bf16 inputs, fp32 accum)
__device__ __forceinline__ void mma_bf16(float* d, const uint32_t* a, const uint32_t* b) {
    asm volatile("mma.sync.aligned.m16n8k16.row.col.f32.bf16.bf16.f32 "
                 "{%0,%1,%2,%3}, {%4,%5,%6,%7}, {%8,%9}, {%0,%1,%2,%3};"
                 : "+f"(d[0]), "+f"(d[1]), "+f"(d[2]), "+f"(d[3])
                 : "r"(a[0]), "r"(a[1]), "r"(a[2]), "r"(a[3]), "r"(b[0]), "r"(b[1]));
}
// async 16B copy global -> shared (sm_80 baseline)
#define CP_ASYNC16(dst_u32, src_ptr) \
    asm volatile("cp.async.cg.shared.global [%0], [%1], 16;" :: "r"(dst_u32), "l"(src_ptr))
#define CP_COMMIT() asm volatile("cp.async.commit_group;" ::: "memory")
#define CP_WAIT(n)  asm volatile("cp.async.wait_group %0;" :: "n"(n) : "memory")

__device__ __forceinline__ void split_bf16(float v, unsigned short& h, unsigned short& l) {
    __nv_bfloat16 bh = __float2bfloat16(v);
    __nv_bfloat16 bl = __float2bfloat16(v - __bfloat162float(bh));
    h = __bfloat16_as_ushort(bh);
    l = __bfloat16_as_ushort(bl);
}
__device__ __forceinline__ int clamp_idx(long long v) {
    if (v < 0) v = 0;
    if (v >= N_NODES) v = N_NODES - 1;
    return (int)v;
}

// ================= fused prep =================
constexpr int NXB  = (int)((size_t)NPAD * CIN / 4 / 256);  // 12512 (exact)
constexpr int WT1B = CIN * C1 / 256;                        // 128 (exact)
constexpr int WT2B = C1 * C2 / 256;                         // 32 (exact)
constexpr int ZB   = (N_NODES + 255) / 256;                 // 196
constexpr int PREP_BLOCKS = NXB + WT1B + WT2B + ZB + 1;

__global__ void prep_kernel(const float* __restrict__ x,
                            const float* __restrict__ W1, const float* __restrict__ W2,
                            const int* __restrict__ ei32) {
    const int b   = blockIdx.x;
    const int tid = threadIdx.x;
    if (b < NXB) {
        size_t i   = (size_t)b * 256 + tid;
        size_t row = i / (CIN / 4);
        float4 v = make_float4(0.f, 0.f, 0.f, 0.f);
        if (row < N_NODES) v = reinterpret_cast<const float4*>(x)[i];
        ushort4 h, l;
        split_bf16(v.x, h.x, l.x);
        split_bf16(v.y, h.y, l.y);
        split_bf16(v.z, h.z, l.z);
        split_bf16(v.w, h.w, l.w);
        reinterpret_cast<ushort4*>(g_xhi)[i] = h;
        reinterpret_cast<ushort4*>(g_xlo)[i] = l;
    } else if (b < NXB + WT1B) {
        int i = (b - NXB) * 256 + tid;
        int n = i / CIN, k = i % CIN;
        unsigned short h, l;
        split_bf16(W1[(size_t)k * C1 + n], h, l);
        g_w1thi[(size_t)n * CIN + k] = __ushort_as_bfloat16(h);
        g_w1tlo[(size_t)n * CIN + k] = __ushort_as_bfloat16(l);
    } else if (b < NXB + WT1B + WT2B) {
        int i = (b - NXB - WT1B) * 256 + tid;
        int n = i / C1, k = i % C1;
        unsigned short h, l;
        split_bf16(W2[(size_t)k * C2 + n], h, l);
        g_w2thi[(size_t)n * C1 + k] = __ushort_as_bfloat16(h);
        g_w2tlo[(size_t)n * C1 + k] = __ushort_as_bfloat16(l);
    } else if (b < NXB + WT1B + WT2B + ZB) {
        int i = (b - NXB - WT1B - WT2B) * 256 + tid;
        if (i < N_NODES) g_deg[i] = 0;
    } else {
        if (tid < 32) {
            int v = ei32[2 * tid + 1];
            unsigned nz = __ballot_sync(0xffffffffu, v != 0);
            if (tid == 0) g_is64 = (nz == 0u) ? 1 : 0;
        }
    }
}

// ================= fused converts: edges + queries =================
__global__ void converts_kernel(const void* __restrict__ ei,
                                const void* __restrict__ pos, const void* __restrict__ neg,
                                int E, int Ep, int En, int EB) {
    const int b   = blockIdx.x;
    const int tid = threadIdx.x;
    const int is64 = g_is64;
    if (b < EB) {
        int e = b * 256 + tid;
        if (e >= E) return;
        int s, d;
        if (is64) {
            const long long* p = (const long long*)ei;
            s = clamp_idx(p[e]);
            d = clamp_idx(p[E + e]);
        } else {
            const int* p = (const int*)ei;
            s = clamp_idx(p[e]);
            d = clamp_idx(p[E + e]);
        }
        g_src[e] = s;
        g_dst[e] = d;
        atomicAdd(&g_deg[d], 1);
    } else {
        int i = (b - EB) * 256 + tid;
        if (i >= Ep + En) return;
        int a, bb;
        if (is64) {
            if (i < Ep) {
                const long long* p = (const long long*)pos;
                a  = clamp_idx(p[i]);
                bb = clamp_idx(p[Ep + i]);
            } else {
                const long long* p = (const long long*)neg;
                a  = clamp_idx(p[i - Ep]);
                bb = clamp_idx(p[En + i - Ep]);
            }
        } else {
            if (i < Ep) {
                const int* p = (const int*)pos;
                a  = clamp_idx(p[i]);
                bb = clamp_idx(p[Ep + i]);
            } else {
                const int* p = (const int*)neg;
                a  = clamp_idx(p[i - Ep]);
                bb = clamp_idx(p[En + i - Ep]);
            }
        }
        g_qa[i] = a;
        g_qb[i] = bb;
    }
}

// ================= scan (+ fused dinv) =================
__global__ void __launch_bounds__(1024) scan_dinv_kernel() {
    __shared__ int wsum[32];
    __shared__ int s_carry;
    const int tid  = threadIdx.x;
    const int lane = tid & 31;
    const int wid  = tid >> 5;
    if (tid == 0) s_carry = 0;
    __syncthreads();
    for (int base = 0; base < N_NODES; base += 1024) {
        int i = base + tid;
        int v = (i < N_NODES) ? g_deg[i] : 0;
        int inc = v;
#pragma unroll
        for (int o = 1; o < 32; o <<= 1) {
            int t = __shfl_up_sync(0xffffffffu, inc, o);
            if (lane >= o) inc += t;
        }
        if (lane == 31) wsum[wid] = inc;
        __syncthreads();
        if (wid == 0) {
            int w = wsum[lane];
            int winc = w;
#pragma unroll
            for (int o = 1; o < 32; o <<= 1) {
                int t = __shfl_up_sync(0xffffffffu, winc, o);
                if (lane >= o) winc += t;
            }
            wsum[lane] = winc;
        }
        __syncthreads();
        int excl = s_carry + ((wid > 0) ? wsum[wid - 1] : 0) + inc - v;
        if (i < N_NODES) {
            g_off[i]  = excl;
            g_cur[i]  = excl;
            g_dinv[i] = rsqrtf((float)(v + 1));   // +1 self-loop
        }
        int chunk_total = wsum[31];
        __syncthreads();
        if (tid == 0) s_carry += chunk_total;
        __syncthreads();
    }
    if (threadIdx.x == 0) g_off[N_NODES] = s_carry;
}

__global__ void fill_kernel(int E) {
    int e = blockIdx.x * blockDim.x + threadIdx.x;
    if (e < E) {
        int pos = atomicAdd(&g_cur[g_dst[e]], 1);
        g_srcidx[pos] = g_src[e];
    }
}

// ================= HMMA GEMM (cp.async double-buffered; R14-proven) =================
template <int N_DIM, int K_DIM>
__global__ void __launch_bounds__(256)
mma_gemm_kernel(const __nv_bfloat16* __restrict__ a_hi, const __nv_bfloat16* __restrict__ a_lo,
                const __nv_bfloat16* __restrict__ b_hi, const __nv_bfloat16* __restrict__ b_lo,
                float* __restrict__ out) {
    constexpr int NCHUNK = K_DIM / 64;
    constexpr int NT     = N_DIM / 8;
    constexpr int A_TILE = 128 * 128;
    constexpr int B_TILE = N_DIM * 128;
    constexpr int S_A_HI = 0;
    constexpr int S_A_LO = A_TILE;
    constexpr int S_B_HI = 2 * A_TILE;
    constexpr int S_B_LO = 2 * A_TILE + B_TILE;
    constexpr int STAGE  = 2 * A_TILE + 2 * B_TILE;

    extern __shared__ char smem[];
    const uint32_t sbase = smem_u32(smem);
    const int tid  = threadIdx.x;
    const int wid  = tid >> 5;
    const int lane = tid & 31;
    const int row0 = blockIdx.x * 128;

    float acc[NT][4];
#pragma unroll
    for (int t = 0; t < NT; t++)
#pragma unroll
        for (int c = 0; c < 4; c++) acc[t][c] = 0.f;

    const int g = lane >> 3, l8 = lane & 7;
    const int a_row = wid * 16 + l8 + ((g & 1) ? 8 : 0);
    const int a_k8  = (g >> 1) ? 8 : 0;
    const int b_nrel = l8 + ((g >> 1) ? 8 : 0);
    const int b_k8   = (g & 1) ? 8 : 0;

    constexpr int KU4 = K_DIM / 8;

    auto stage = [&](int kc, int buf) {
        const uint32_t SB = sbase + buf * STAGE;
#pragma unroll
        for (int li = 0; li < 4; li++) {
            int f = tid + li * 256;
            int r = f >> 3, c16 = f & 7;
            uint32_t sw = sw128((uint32_t)(r * 128 + c16 * 16));
            size_t gi = (size_t)(row0 + r) * KU4 + (size_t)kc * 8 + c16;
            CP_ASYNC16(SB + S_A_HI + sw, reinterpret_cast<const uint4*>(a_hi) + gi);
            CP_ASYNC16(SB + S_A_LO + sw, reinterpret_cast<const uint4*>(a_lo) + gi);
        }
#pragma unroll
        for (int f = tid; f < N_DIM * 8; f += 256) {
            int n = f >> 3, c16 = f & 7;
            uint32_t sw = sw128((uint32_t)(n * 128 + c16 * 16));
            size_t gi = (size_t)n * KU4 + (size_t)kc * 8 + c16;
            CP_ASYNC16(SB + S_B_HI + sw, reinterpret_cast<const uint4*>(b_hi) + gi);
            CP_ASYNC16(SB + S_B_LO + sw, reinterpret_cast<const uint4*>(b_lo) + gi);
        }
        CP_COMMIT();
    };

    stage(0, 0);

    for (int kc = 0; kc < NCHUNK; kc++) {
        const int buf = kc & 1;
        if (kc > 0) __syncthreads();
        if (kc + 1 < NCHUNK) {
            stage(kc + 1, buf ^ 1);
            CP_WAIT(1);
        } else {
            CP_WAIT(0);
        }
        __syncthreads();

        const uint32_t SB = sbase + buf * STAGE;
#pragma unroll
        for (int ks = 0; ks < 4; ks++) {
            uint32_t ah[4], al[4];
            uint32_t a_off = sw128((uint32_t)(a_row * 128 + (ks * 16 + a_k8) * 2));
            ldsm_x4(ah, SB + S_A_HI + a_off);
            ldsm_x4(al, SB + S_A_LO + a_off);
#pragma unroll
            for (int np = 0; np < NT / 2; np++) {
                uint32_t bh[4], bl[4];
                uint32_t b_off = sw128((uint32_t)((np * 16 + b_nrel) * 128 + (ks * 16 + b_k8) * 2));
                ldsm_x4(bh, SB + S_B_HI + b_off);
                ldsm_x4(bl, SB + S_B_LO + b_off);
                mma_bf16(acc[2 * np],     ah, bh);
                mma_bf16(acc[2 * np + 1], ah, bh + 2);
                mma_bf16(acc[2 * np],     ah, bl);
                mma_bf16(acc[2 * np + 1], ah, bl + 2);
                mma_bf16(acc[2 * np],     al, bh);
                mma_bf16(acc[2 * np + 1], al, bh + 2);
            }
        }
    }

    const size_t rlo  = (size_t)row0 + wid * 16 + (lane >> 2);
    const int    col0 = (lane & 3) * 2;
#pragma unroll
    for (int nt = 0; nt < NT; nt++) {
        float2 v0 = make_float2(acc[nt][0], acc[nt][1]);
        float2 v1 = make_float2(acc[nt][2], acc[nt][3]);
        *reinterpret_cast<float2*>(&out[rlo * N_DIM + nt * 8 + col0])       = v0;
        *reinterpret_cast<float2*>(&out[(rlo + 8) * N_DIM + nt * 8 + col0]) = v1;
    }
}

// ================= gather + combine (R14-proven) =================
__global__ void gather128_kernel(const float* __restrict__ hs,
                                 const float* __restrict__ bias) {
    int gw   = (blockIdx.x * blockDim.x + threadIdx.x) >> 5;
    int lane = threadIdx.x & 31;
    if (gw >= NPAD) return;
    ushort4* hrow = reinterpret_cast<ushort4*>(g_hhi + (size_t)gw * C1);
    ushort4* lrow = reinterpret_cast<ushort4*>(g_hlo + (size_t)gw * C1);
    if (gw >= N_NODES) {
        ushort4 zz = make_ushort4(0, 0, 0, 0);
        hrow[lane] = zz;
        lrow[lane] = zz;
        return;
    }
    const int s = g_off[gw];
    const int e = g_off[gw + 1];
    const float dself = g_dinv[gw];

    float4 self = *reinterpret_cast<const float4*>(&hs[(size_t)gw * C1 + lane * 4]);
    float4 acc;
    acc.x = self.x * dself;
    acc.y = self.y * dself;
    acc.z = self.z * dself;
    acc.w = self.w * dself;

    int k = s;
    for (; k + 4 <= e; k += 4) {
        int s0 = g_srcidx[k + 0];
        int s1 = g_srcidx[k + 1];
        int s2 = g_srcidx[k + 2];
        int s3 = g_srcidx[k + 3];
        float d0 = g_dinv[s0], d1 = g_dinv[s1], d2 = g_dinv[s2], d3 = g_dinv[s3];
        float4 v0 = *reinterpret_cast<const float4*>(&hs[(size_t)s0 * C1 + lane * 4]);
        float4 v1 = *reinterpret_cast<const float4*>(&hs[(size_t)s1 * C1 + lane * 4]);
        float4 v2 = *reinterpret_cast<const float4*>(&hs[(size_t)s2 * C1 + lane * 4]);
        float4 v3 = *reinterpret_cast<const float4*>(&hs[(size_t)s3 * C1 + lane * 4]);
        acc.x += v0.x * d0 + v1.x * d1 + v2.x * d2 + v3.x * d3;
        acc.y += v0.y * d0 + v1.y * d1 + v2.y * d2 + v3.y * d3;
        acc.z += v0.z * d0 + v1.z * d1 + v2.z * d2 + v3.z * d3;
        acc.w += v0.w * d0 + v1.w * d1 + v2.w * d2 + v3.w * d3;
    }
    for (; k < e; k++) {
        int sk = g_srcidx[k];
        float dk = g_dinv[sk];
        float4 v = *reinterpret_cast<const float4*>(&hs[(size_t)sk * C1 + lane * 4]);
        acc.x += v.x * dk; acc.y += v.y * dk; acc.z += v.z * dk; acc.w += v.w * dk;
    }

    float4 b = *reinterpret_cast<const float4*>(&bias[lane * 4]);
    float4 o;
    o.x = fmaxf(dself * acc.x + b.x, 0.f);
    o.y = fmaxf(dself * acc.y + b.y, 0.f);
    o.z = fmaxf(dself * acc.z + b.z, 0.f);
    o.w = fmaxf(dself * acc.w + b.w, 0.f);

    ushort4 hv, lv;
    split_bf16(o.x, hv.x, lv.x);
    split_bf16(o.y, hv.y, lv.y);
    split_bf16(o.z, hv.z, lv.z);
    split_bf16(o.w, hv.w, lv.w);
    hrow[lane] = hv;
    lrow[lane] = lv;
}

__global__ void gather64_kernel(const float* __restrict__ hs, float* __restrict__ out,
                                const float* __restrict__ bias) {
    int gw   = (blockIdx.x * blockDim.x + threadIdx.x) >> 5;
    int lane = threadIdx.x & 31;
    if (gw >= N_NODES) return;
    const int s = g_off[gw];
    const int e = g_off[gw + 1];
    const float dself = g_dinv[gw];

    float2 self = *reinterpret_cast<const float2*>(&hs[(size_t)gw * C2 + lane * 2]);
    float2 acc;
    acc.x = self.x * dself;
    acc.y = self.y * dself;

    int k = s;
    for (; k + 4 <= e; k += 4) {
        int s0 = g_srcidx[k + 0];
        int s1 = g_srcidx[k + 1];
        int s2 = g_srcidx[k + 2];
        int s3 = g_srcidx[k + 3];
        float d0 = g_dinv[s0], d1 = g_dinv[s1], d2 = g_dinv[s2], d3 = g_dinv[s3];
        float2 v0 = *reinterpret_cast<const float2*>(&hs[(size_t)s0 * C2 + lane * 2]);
        float2 v1 = *reinterpret_cast<const float2*>(&hs[(size_t)s1 * C2 + lane * 2]);
        float2 v2 = *reinterpret_cast<const float2*>(&hs[(size_t)s2 * C2 + lane * 2]);
        float2 v3 = *reinterpret_cast<const float2*>(&hs[(size_t)s3 * C2 + lane * 2]);
        acc.x += v0.x * d0 + v1.x * d1 + v2.x * d2 + v3.x * d3;
        acc.y += v0.y * d0 + v1.y * d1 + v2.y * d2 + v3.y * d3;
    }
    for (; k < e; k++) {
        int sk = g_srcidx[k];
        float dk = g_dinv[sk];
        float2 v = *reinterpret_cast<const float2*>(&hs[(size_t)sk * C2 + lane * 2]);
        acc.x += v.x * dk; acc.y += v.y * dk;
    }

    float2 b = *reinterpret_cast<const float2*>(&bias[lane * 2]);
    float2 o;
    o.x = dself * acc.x + b.x;
    o.y = dself * acc.y + b.y;
    *reinterpret_cast<float2*>(&out[(size_t)gw * C2 + lane * 2]) = o;
}

// ---------------- logits ----------------
__global__ void logits_kernel(int Q, const float* __restrict__ z, float* __restrict__ out) {
    long long idx = (long long)blockIdx.x * blockDim.x + threadIdx.x;
    long long e = idx / 16;
    int j       = (int)(idx % 16);
    if (e >= Q) return;
    int a = g_qa[e];
    int b = g_qb[e];
    float4 va = *reinterpret_cast<const float4*>(&z[(size_t)a * C2 + j * 4]);
    float4 vb = *reinterpret_cast<const float4*>(&z[(size_t)b * C2 + j * 4]);
    float d = va.x * vb.x + va.y * vb.y + va.z * vb.z + va.w * vb.w;
#pragma unroll
    for (int off = 8; off > 0; off >>= 1)
        d += __shfl_xor_sync(0xffffffffu, d, off, 16);
    if (j == 0) out[e] = d;
}

// ---------------- launch ----------------
extern "C" void kernel_launch(void* const* d_in, const int* in_sizes, int n_in,
                              void* d_out, int out_size) {
    const float* x   = (const float*)d_in[0];
    const void*  ei  = d_in[1];
    const void*  pos = d_in[2];
    const void*  neg = d_in[3];
    const float* W1  = (const float*)d_in[4];
    const float* b1  = (const float*)d_in[5];
    const float* W2  = (const float*)d_in[6];
    const float* b2  = (const float*)d_in[7];
    float* out = (float*)d_out;

    const int E  = in_sizes[1] / 2;
    const int Ep = in_sizes[2] / 2;
    const int En = in_sizes[3] / 2;
    const int Q  = Ep + En;

    float *hs1, *hs2, *z;
    __nv_bfloat16 *xhi, *xlo, *w1thi, *w1tlo, *hhi, *hlo, *w2thi, *w2tlo;
    cudaGetSymbolAddress((void**)&hs1,   g_hs1);
    cudaGetSymbolAddress((void**)&hs2,   g_hs2);
    cudaGetSymbolAddress((void**)&z,     g_z);
    cudaGetSymbolAddress((void**)&xhi,   g_xhi);
    cudaGetSymbolAddress((void**)&xlo,   g_xlo);
    cudaGetSymbolAddress((void**)&w1thi, g_w1thi);
    cudaGetSymbolAddress((void**)&w1tlo, g_w1tlo);
    cudaGetSymbolAddress((void**)&hhi,   g_hhi);
    cudaGetSymbolAddress((void**)&hlo,   g_hlo);
    cudaGetSymbolAddress((void**)&w2thi, g_w2thi);
    cudaGetSymbolAddress((void**)&w2tlo, g_w2tlo);

    constexpr int SMEM1 = 2 * (2 * (128 * 128) + 2 * (C1 * 128));  // 131072
    constexpr int SMEM2 = 2 * (2 * (128 * 128) + 2 * (C2 * 128));  // 98304
    cudaFuncSetAttribute(mma_gemm_kernel<C1, CIN>, cudaFuncAttributeMaxDynamicSharedMemorySize, SMEM1);
    cudaFuncSetAttribute(mma_gemm_kernel<C2, C1>,  cudaFuncAttributeMaxDynamicSharedMemorySize, SMEM2);

    // side stream + fork/join events (created once, on the uncaptured correctness call)
    static cudaStream_t s2 = nullptr;
    static cudaEvent_t evFork = nullptr, evJoin = nullptr;
    if (!s2) {
        cudaStreamCreateWithFlags(&s2, cudaStreamNonBlocking);
        cudaEventCreateWithFlags(&evFork, cudaEventDisableTiming);
        cudaEventCreateWithFlags(&evJoin, cudaEventDisableTiming);
    }

    const int NTILES = NPAD / 128;        // 391
    const int EB = (E + 255) / 256;       // 3125
    const int QB = (Q + 255) / 256;       // 1563

    // main stream: prep -> GEMM1 ----------------------------> gather128 -> ...
    // side stream:        \-> converts -> scan -> fill  --/
    prep_kernel<<<PREP_BLOCKS, 256>>>(x, W1, W2, (const int*)ei);                    // launch 0
    cudaEventRecord(evFork, 0);
    cudaStreamWaitEvent(s2, evFork, 0);

    converts_kernel<<<EB + QB, 256, 0, s2>>>(ei, pos, neg, E, Ep, En, EB);           // launch 1
    scan_dinv_kernel<<<1, 1024, 0, s2>>>();                                           // launch 2
    mma_gemm_kernel<C1, CIN><<<NTILES, 256, SMEM1>>>(xhi, xlo, w1thi, w1tlo, hs1);   // launch 3 (profiled slot)
    fill_kernel<<<EB, 256, 0, s2>>>(E);                                               // launch 4
    cudaEventRecord(evJoin, s2);
    cudaStreamWaitEvent(0, evJoin, 0);

    gather128_kernel<<<(NPAD * 32 + 255) / 256, 256>>>(hs1, b1);                      // launch 5
    mma_gemm_kernel<C2, C1><<<NTILES, 256, SMEM2>>>(hhi, hlo, w2thi, w2tlo, hs2);    // launch 6
    gather64_kernel<<<(N_NODES * 32 + 255) / 256, 256>>>(hs2, z, b2);                 // launch 7
    {
        long long tot = (long long)Q * 16;
        logits_kernel<<<(int)((tot + 255) / 256), 256>>>(Q, z, out);                  // launch 8
    }
}

// round 17
// speedup vs baseline: 2.0461x; 1.0338x over previous
#include <cuda_runtime.h>
#include <cuda_bf16.h>
#include <cstdint>

// ---------------- problem constants ----------------
#define N_NODES 50000
#define E_MAX   800000
#define Q_MAX   400000
constexpr int CIN  = 256;   // input channels
constexpr int C1   = 128;   // hidden channels
constexpr int C2   = 64;    // output channels
constexpr int NPAD = 50048; // 391 * 128 (padded rows for 128-row GEMM tiles)

// ---------------- device scratch (static; no allocs allowed) ----------------
__device__ int g_is64;
__device__ __align__(16) int   g_src   [E_MAX];
__device__ __align__(16) int   g_dst   [E_MAX];
__device__ __align__(16) int   g_qa    [Q_MAX];
__device__ __align__(16) int   g_qb    [Q_MAX];
__device__ __align__(16) int   g_deg   [N_NODES];
__device__ __align__(16) int   g_off   [N_NODES + 1];
__device__ __align__(16) int   g_cur   [N_NODES];
__device__ __align__(16) int   g_srcidx[E_MAX];
__device__ __align__(16) float g_dinv  [N_NODES];
// bf16 hi/lo split weights (tiny; prestaged)
__device__ __align__(16) __nv_bfloat16 g_w1thi[(size_t)C1 * CIN];   // W1^T [C1][CIN]
__device__ __align__(16) __nv_bfloat16 g_w1tlo[(size_t)C1 * CIN];
__device__ __align__(16) __nv_bfloat16 g_w2thi[(size_t)C2 * C1];    // W2^T [C2][C1]
__device__ __align__(16) __nv_bfloat16 g_w2tlo[(size_t)C2 * C1];
// fp32 intermediates (GEMMs convert A fp32->bf16 hi/lo in-register during staging)
__device__ __align__(16) float g_hs1[(size_t)NPAD * C1];      // x @ W1
__device__ __align__(16) float g_h  [(size_t)N_NODES * C1];   // relu layer-1 output
__device__ __align__(16) float g_hs2[(size_t)NPAD * C2];      // h @ W2
__device__ __align__(16) float g_z  [(size_t)N_NODES * C2];   // layer-2 output

// ---------------- helpers ----------------
__device__ __forceinline__ uint32_t smem_u32(const void* p) {
    uint32_t a;
    asm("{ .reg .u64 t; cvta.to.shared.u64 t, %1; cvt.u32.u64 %0, t; }" : "=r"(a) : "l"(p));
    return a;
}
__device__ __forceinline__ uint32_t sw128(uint32_t off) { return off ^ ((off >> 3) & 0x70); }

__device__ __forceinline__ void ldsm_x4(uint32_t* r, uint32_t addr) {
    asm volatile("ldmatrix.sync.aligned.m8n8.x4.shared.b16 {%0,%1,%2,%3}, [%4];"
                 : "=r"(r[0]), "=r"(r[1]), "=r"(r[2]), "=r"(r[3]) : "r"(addr));
}
// D += A * B  (m16n8k16, bf16 inputs, fp32 accum)
__device__ __forceinline__ void mma_bf16(float* d, const uint32_t* a, const uint32_t* b) {
    asm volatile("mma.sync.aligned.m16n8k16.row.col.f32.bf16.bf16.f32 "
                 "{%0,%1,%2,%3}, {%4,%5,%6,%7}, {%8,%9}, {%0,%1,%2,%3};"
                 : "+f"(d[0]), "+f"(d[1]), "+f"(d[2]), "+f"(d[3])
                 : "r"(a[0]), "r"(a[1]), "r"(a[2]), "r"(a[3]), "r"(b[0]), "r"(b[1]));
}
// async 16B copy global -> shared (sm_80 baseline)
#define CP_ASYNC16(dst_u32, src_ptr) \
    asm volatile("cp.async.cg.shared.global [%0], [%1], 16;" :: "r"(dst_u32), "l"(src_ptr))
#define CP_COMMIT() asm volatile("cp.async.commit_group;" ::: "memory")
#define CP_WAIT(n)  asm volatile("cp.async.wait_group %0;" :: "n"(n) : "memory")

__device__ __forceinline__ void split_bf16(float v, unsigned short& h, unsigned short& l) {
    __nv_bfloat16 bh = __float2bfloat16(v);
    __nv_bfloat16 bl = __float2bfloat16(v - __bfloat162float(bh));
    h = __bfloat16_as_ushort(bh);
    l = __bfloat16_as_ushort(bl);
}
__device__ __forceinline__ unsigned pack2(unsigned short a, unsigned short b) {
    return (unsigned)a | ((unsigned)b << 16);
}
__device__ __forceinline__ int clamp_idx(long long v) {
    if (v < 0) v = 0;
    if (v >= N_NODES) v = N_NODES - 1;
    return (int)v;
}

// ================= fused prep (weights split + zero_deg + detect; tiny now) =================
constexpr int WT1B = CIN * C1 / 256;            // 128 (exact)
constexpr int WT2B = C1 * C2 / 256;             // 32 (exact)
constexpr int ZB   = (N_NODES + 255) / 256;     // 196
constexpr int PREP_BLOCKS = WT1B + WT2B + ZB + 1;

__global__ void prep_kernel(const float* __restrict__ W1, const float* __restrict__ W2,
                            const int* __restrict__ ei32) {
    const int b   = blockIdx.x;
    const int tid = threadIdx.x;
    if (b < WT1B) {
        int i = b * 256 + tid;
        int n = i / CIN, k = i % CIN;
        unsigned short h, l;
        split_bf16(W1[(size_t)k * C1 + n], h, l);
        g_w1thi[(size_t)n * CIN + k] = __ushort_as_bfloat16(h);
        g_w1tlo[(size_t)n * CIN + k] = __ushort_as_bfloat16(l);
    } else if (b < WT1B + WT2B) {
        int i = (b - WT1B) * 256 + tid;
        int n = i / C1, k = i % C1;
        unsigned short h, l;
        split_bf16(W2[(size_t)k * C2 + n], h, l);
        g_w2thi[(size_t)n * C1 + k] = __ushort_as_bfloat16(h);
        g_w2tlo[(size_t)n * C1 + k] = __ushort_as_bfloat16(l);
    } else if (b < WT1B + WT2B + ZB) {
        int i = (b - WT1B - WT2B) * 256 + tid;
        if (i < N_NODES) g_deg[i] = 0;
    } else {
        if (tid < 32) {
            int v = ei32[2 * tid + 1];
            unsigned nz = __ballot_sync(0xffffffffu, v != 0);
            if (tid == 0) g_is64 = (nz == 0u) ? 1 : 0;
        }
    }
}

// ================= fused converts: edges + queries =================
__global__ void converts_kernel(const void* __restrict__ ei,
                                const void* __restrict__ pos, const void* __restrict__ neg,
                                int E, int Ep, int En, int EB) {
    const int b   = blockIdx.x;
    const int tid = threadIdx.x;
    const int is64 = g_is64;
    if (b < EB) {
        int e = b * 256 + tid;
        if (e >= E) return;
        int s, d;
        if (is64) {
            const long long* p = (const long long*)ei;
            s = clamp_idx(p[e]);
            d = clamp_idx(p[E + e]);
        } else {
            const int* p = (const int*)ei;
            s = clamp_idx(p[e]);
            d = clamp_idx(p[E + e]);
        }
        g_src[e] = s;
        g_dst[e] = d;
        atomicAdd(&g_deg[d], 1);
    } else {
        int i = (b - EB) * 256 + tid;
        if (i >= Ep + En) return;
        int a, bb;
        if (is64) {
            if (i < Ep) {
                const long long* p = (const long long*)pos;
                a  = clamp_idx(p[i]);
                bb = clamp_idx(p[Ep + i]);
            } else {
                const long long* p = (const long long*)neg;
                a  = clamp_idx(p[i - Ep]);
                bb = clamp_idx(p[En + i - Ep]);
            }
        } else {
            if (i < Ep) {
                const int* p = (const int*)pos;
                a  = clamp_idx(p[i]);
                bb = clamp_idx(p[Ep + i]);
            } else {
                const int* p = (const int*)neg;
                a  = clamp_idx(p[i - Ep]);
                bb = clamp_idx(p[En + i - Ep]);
            }
        }
        g_qa[i] = a;
        g_qb[i] = bb;
    }
}

// ================= scan (+ fused dinv) =================
__global__ void __launch_bounds__(1024) scan_dinv_kernel() {
    __shared__ int wsum[32];
    __shared__ int s_carry;
    const int tid  = threadIdx.x;
    const int lane = tid & 31;
    const int wid  = tid >> 5;
    if (tid == 0) s_carry = 0;
    __syncthreads();
    for (int base = 0; base < N_NODES; base += 1024) {
        int i = base + tid;
        int v = (i < N_NODES) ? g_deg[i] : 0;
        int inc = v;
#pragma unroll
        for (int o = 1; o < 32; o <<= 1) {
            int t = __shfl_up_sync(0xffffffffu, inc, o);
            if (lane >= o) inc += t;
        }
        if (lane == 31) wsum[wid] = inc;
        __syncthreads();
        if (wid == 0) {
            int w = wsum[lane];
            int winc = w;
#pragma unroll
            for (int o = 1; o < 32; o <<= 1) {
                int t = __shfl_up_sync(0xffffffffu, winc, o);
                if (lane >= o) winc += t;
            }
            wsum[lane] = winc;
        }
        __syncthreads();
        int excl = s_carry + ((wid > 0) ? wsum[wid - 1] : 0) + inc - v;
        if (i < N_NODES) {
            g_off[i]  = excl;
            g_cur[i]  = excl;
            g_dinv[i] = rsqrtf((float)(v + 1));   // +1 self-loop
        }
        int chunk_total = wsum[31];
        __syncthreads();
        if (tid == 0) s_carry += chunk_total;
        __syncthreads();
    }
    if (threadIdx.x == 0) g_off[N_NODES] = s_carry;
}

__global__ void fill_kernel(int E) {
    int e = blockIdx.x * blockDim.x + threadIdx.x;
    if (e < E) {
        int pos = atomicAdd(&g_cur[g_dst[e]], 1);
        g_srcidx[pos] = g_src[e];
    }
}

// ================= HMMA GEMM, fp32 A with in-register bf16 hi/lo split =================
// out[NPAD, N_DIM] = A @ B^T. A: [M_real, K_DIM] fp32 (rows >= M_real treated as 0),
// B: [N_DIM, K_DIM] bf16 hi/lo. 3 accumulate passes: Ah*Bh + Ah*Bl + Al*Bh.
// CTA: 128 rows, 256 threads = 8 warps; warp w owns rows [w*16, w*16+16).
// A is prefetched one k-chunk ahead into registers (8x float4/thread), split, STS'd.
template <int N_DIM, int K_DIM>
__global__ void __launch_bounds__(256)
mma_gemm_kernel(const float* __restrict__ A,
                const __nv_bfloat16* __restrict__ b_hi, const __nv_bfloat16* __restrict__ b_lo,
                float* __restrict__ out, int M_real) {
    constexpr int NCHUNK = K_DIM / 64;
    constexpr int NT     = N_DIM / 8;
    constexpr int A_TILE = 128 * 128;
    constexpr int B_TILE = N_DIM * 128;
    constexpr int S_A_HI = 0;
    constexpr int S_A_LO = A_TILE;
    constexpr int S_B_HI = 2 * A_TILE;
    constexpr int S_B_LO = 2 * A_TILE + B_TILE;
    constexpr int STAGE  = 2 * A_TILE + 2 * B_TILE;

    extern __shared__ char smem[];
    const uint32_t sbase = smem_u32(smem);
    const int tid  = threadIdx.x;
    const int wid  = tid >> 5;
    const int lane = tid & 31;
    const int row0 = blockIdx.x * 128;

    float acc[NT][4];
#pragma unroll
    for (int t = 0; t < NT; t++)
#pragma unroll
        for (int c = 0; c < 4; c++) acc[t][c] = 0.f;

    const int g = lane >> 3, l8 = lane & 7;
    const int a_row = wid * 16 + l8 + ((g & 1) ? 8 : 0);
    const int a_k8  = (g >> 1) ? 8 : 0;
    const int b_nrel = l8 + ((g >> 1) ? 8 : 0);
    const int b_k8   = (g & 1) ? 8 : 0;

    constexpr int KU4 = K_DIM / 8;   // uint4 (8 bf16) per B row

    // A prefetch registers: 4 fragments x 8 fp32
    float4 axa[4], axb[4];
    const float4 z4 = make_float4(0.f, 0.f, 0.f, 0.f);

    auto ldgA = [&](int kc) {
#pragma unroll
        for (int li = 0; li < 4; li++) {
            int f = tid + li * 256;
            int r = f >> 3, c16 = f & 7;
            int grow = row0 + r;
            if (grow < M_real) {
                const float4* src = reinterpret_cast<const float4*>(
                    &A[(size_t)grow * K_DIM + kc * 64 + c16 * 8]);
                axa[li] = src[0];
                axb[li] = src[1];
            } else {
                axa[li] = z4;
                axb[li] = z4;
            }
        }
    };
    auto stsA = [&](int buf) {
        char* SB = smem + buf * STAGE;
#pragma unroll
        for (int li = 0; li < 4; li++) {
            int f = tid + li * 256;
            int r = f >> 3, c16 = f & 7;
            uint32_t sw = sw128((uint32_t)(r * 128 + c16 * 16));
            unsigned short h[8], l[8];
            split_bf16(axa[li].x, h[0], l[0]);
            split_bf16(axa[li].y, h[1], l[1]);
            split_bf16(axa[li].z, h[2], l[2]);
            split_bf16(axa[li].w, h[3], l[3]);
            split_bf16(axb[li].x, h[4], l[4]);
            split_bf16(axb[li].y, h[5], l[5]);
            split_bf16(axb[li].z, h[6], l[6]);
            split_bf16(axb[li].w, h[7], l[7]);
            uint4 hv = make_uint4(pack2(h[0], h[1]), pack2(h[2], h[3]),
                                  pack2(h[4], h[5]), pack2(h[6], h[7]));
            uint4 lv = make_uint4(pack2(l[0], l[1]), pack2(l[2], l[3]),
                                  pack2(l[4], l[5]), pack2(l[6], l[7]));
            *reinterpret_cast<uint4*>(SB + S_A_HI + sw) = hv;
            *reinterpret_cast<uint4*>(SB + S_A_LO + sw) = lv;
        }
    };
    auto stageB = [&](int kc, int buf) {
        const uint32_t SB = sbase + buf * STAGE;
#pragma unroll
        for (int f = tid; f < N_DIM * 8; f += 256) {
            int n = f >> 3, c16 = f & 7;
            uint32_t sw = sw128((uint32_t)(n * 128 + c16 * 16));
            size_t gi = (size_t)n * KU4 + (size_t)kc * 8 + c16;
            CP_ASYNC16(SB + S_B_HI + sw, reinterpret_cast<const uint4*>(b_hi) + gi);
            CP_ASYNC16(SB + S_B_LO + sw, reinterpret_cast<const uint4*>(b_lo) + gi);
        }
        CP_COMMIT();
    };

    ldgA(0);
    stageB(0, 0);

    for (int kc = 0; kc < NCHUNK; kc++) {
        const int buf = kc & 1;
        if (kc > 0) __syncthreads();          // compute(kc-1) done; buf free for A-sts
        stsA(buf);                             // A(kc) regs -> smem
        if (kc + 1 < NCHUNK) {
            ldgA(kc + 1);                      // prefetch next A into regs (overlaps compute)
            stageB(kc + 1, buf ^ 1);
            CP_WAIT(1);                        // B(kc) resident; B(kc+1) in flight
        } else {
            CP_WAIT(0);
        }
        __syncthreads();                       // A-sts + B(kc) visible

        const uint32_t SB = sbase + buf * STAGE;
#pragma unroll
        for (int ks = 0; ks < 4; ks++) {
            uint32_t ah[4], al[4];
            uint32_t a_off = sw128((uint32_t)(a_row * 128 + (ks * 16 + a_k8) * 2));
            ldsm_x4(ah, SB + S_A_HI + a_off);
            ldsm_x4(al, SB + S_A_LO + a_off);
#pragma unroll
            for (int np = 0; np < NT / 2; np++) {
                uint32_t bh[4], bl[4];
                uint32_t b_off = sw128((uint32_t)((np * 16 + b_nrel) * 128 + (ks * 16 + b_k8) * 2));
                ldsm_x4(bh, SB + S_B_HI + b_off);
                ldsm_x4(bl, SB + S_B_LO + b_off);
                mma_bf16(acc[2 * np],     ah, bh);
                mma_bf16(acc[2 * np + 1], ah, bh + 2);
                mma_bf16(acc[2 * np],     ah, bl);
                mma_bf16(acc[2 * np + 1], ah, bl + 2);
                mma_bf16(acc[2 * np],     al, bh);
                mma_bf16(acc[2 * np + 1], al, bh + 2);
            }
        }
    }

    const size_t rlo  = (size_t)row0 + wid * 16 + (lane >> 2);
    const int    col0 = (lane & 3) * 2;
#pragma unroll
    for (int nt = 0; nt < NT; nt++) {
        float2 v0 = make_float2(acc[nt][0], acc[nt][1]);
        float2 v1 = make_float2(acc[nt][2], acc[nt][3]);
        *reinterpret_cast<float2*>(&out[rlo * N_DIM + nt * 8 + col0])       = v0;
        *reinterpret_cast<float2*>(&out[(rlo + 8) * N_DIM + nt * 8 + col0]) = v1;
    }
}

// ================= gather + combine =================
// C=128: one warp per node; writes fp32 h (GEMM2 converts during staging)
__global__ void gather128_kernel(const float* __restrict__ hs,
                                 const float* __restrict__ bias) {
    int gw   = (blockIdx.x * blockDim.x + threadIdx.x) >> 5;
    int lane = threadIdx.x & 31;
    if (gw >= N_NODES) return;
    const int s = g_off[gw];
    const int e = g_off[gw + 1];
    const float dself = g_dinv[gw];

    float4 self = *reinterpret_cast<const float4*>(&hs[(size_t)gw * C1 + lane * 4]);
    float4 acc;
    acc.x = self.x * dself;
    acc.y = self.y * dself;
    acc.z = self.z * dself;
    acc.w = self.w * dself;

    int k = s;
    for (; k + 4 <= e; k += 4) {
        int s0 = g_srcidx[k + 0];
        int s1 = g_srcidx[k + 1];
        int s2 = g_srcidx[k + 2];
        int s3 = g_srcidx[k + 3];
        float d0 = g_dinv[s0], d1 = g_dinv[s1], d2 = g_dinv[s2], d3 = g_dinv[s3];
        float4 v0 = *reinterpret_cast<const float4*>(&hs[(size_t)s0 * C1 + lane * 4]);
        float4 v1 = *reinterpret_cast<const float4*>(&hs[(size_t)s1 * C1 + lane * 4]);
        float4 v2 = *reinterpret_cast<const float4*>(&hs[(size_t)s2 * C1 + lane * 4]);
        float4 v3 = *reinterpret_cast<const float4*>(&hs[(size_t)s3 * C1 + lane * 4]);
        acc.x += v0.x * d0 + v1.x * d1 + v2.x * d2 + v3.x * d3;
        acc.y += v0.y * d0 + v1.y * d1 + v2.y * d2 + v3.y * d3;
        acc.z += v0.z * d0 + v1.z * d1 + v2.z * d2 + v3.z * d3;
        acc.w += v0.w * d0 + v1.w * d1 + v2.w * d2 + v3.w * d3;
    }
    for (; k < e; k++) {
        int sk = g_srcidx[k];
        float dk = g_dinv[sk];
        float4 v = *reinterpret_cast<const float4*>(&hs[(size_t)sk * C1 + lane * 4]);
        acc.x += v.x * dk; acc.y += v.y * dk; acc.z += v.z * dk; acc.w += v.w * dk;
    }

    float4 b = *reinterpret_cast<const float4*>(&bias[lane * 4]);
    float4 o;
    o.x = fmaxf(dself * acc.x + b.x, 0.f);
    o.y = fmaxf(dself * acc.y + b.y, 0.f);
    o.z = fmaxf(dself * acc.z + b.z, 0.f);
    o.w = fmaxf(dself * acc.w + b.w, 0.f);
    *reinterpret_cast<float4*>(&g_h[(size_t)gw * C1 + lane * 4]) = o;
}

__global__ void gather64_kernel(const float* __restrict__ hs, float* __restrict__ out,
                                const float* __restrict__ bias) {
    int gw   = (blockIdx.x * blockDim.x + threadIdx.x) >> 5;
    int lane = threadIdx.x & 31;
    if (gw >= N_NODES) return;
    const int s = g_off[gw];
    const int e = g_off[gw + 1];
    const float dself = g_dinv[gw];

    float2 self = *reinterpret_cast<const float2*>(&hs[(size_t)gw * C2 + lane * 2]);
    float2 acc;
    acc.x = self.x * dself;
    acc.y = self.y * dself;

    int k = s;
    for (; k + 4 <= e; k += 4) {
        int s0 = g_srcidx[k + 0];
        int s1 = g_srcidx[k + 1];
        int s2 = g_srcidx[k + 2];
        int s3 = g_srcidx[k + 3];
        float d0 = g_dinv[s0], d1 = g_dinv[s1], d2 = g_dinv[s2], d3 = g_dinv[s3];
        float2 v0 = *reinterpret_cast<const float2*>(&hs[(size_t)s0 * C2 + lane * 2]);
        float2 v1 = *reinterpret_cast<const float2*>(&hs[(size_t)s1 * C2 + lane * 2]);
        float2 v2 = *reinterpret_cast<const float2*>(&hs[(size_t)s2 * C2 + lane * 2]);
        float2 v3 = *reinterpret_cast<const float2*>(&hs[(size_t)s3 * C2 + lane * 2]);
        acc.x += v0.x * d0 + v1.x * d1 + v2.x * d2 + v3.x * d3;
        acc.y += v0.y * d0 + v1.y * d1 + v2.y * d2 + v3.y * d3;
    }
    for (; k < e; k++) {
        int sk = g_srcidx[k];
        float dk = g_dinv[sk];
        float2 v = *reinterpret_cast<const float2*>(&hs[(size_t)sk * C2 + lane * 2]);
        acc.x += v.x * dk; acc.y += v.y * dk;
    }

    float2 b = *reinterpret_cast<const float2*>(&bias[lane * 2]);
    float2 o;
    o.x = dself * acc.x + b.x;
    o.y = dself * acc.y + b.y;
    *reinterpret_cast<float2*>(&out[(size_t)gw * C2 + lane * 2]) = o;
}

// ---------------- logits ----------------
__global__ void logits_kernel(int Q, const float* __restrict__ z, float* __restrict__ out) {
    long long idx = (long long)blockIdx.x * blockDim.x + threadIdx.x;
    long long e = idx / 16;
    int j       = (int)(idx % 16);
    if (e >= Q) return;
    int a = g_qa[e];
    int b = g_qb[e];
    float4 va = *reinterpret_cast<const float4*>(&z[(size_t)a * C2 + j * 4]);
    float4 vb = *reinterpret_cast<const float4*>(&z[(size_t)b * C2 + j * 4]);
    float d = va.x * vb.x + va.y * vb.y + va.z * vb.z + va.w * vb.w;
#pragma unroll
    for (int off = 8; off > 0; off >>= 1)
        d += __shfl_xor_sync(0xffffffffu, d, off, 16);
    if (j == 0) out[e] = d;
}

// ---------------- launch ----------------
extern "C" void kernel_launch(void* const* d_in, const int* in_sizes, int n_in,
                              void* d_out, int out_size) {
    const float* x   = (const float*)d_in[0];
    const void*  ei  = d_in[1];
    const void*  pos = d_in[2];
    const void*  neg = d_in[3];
    const float* W1  = (const float*)d_in[4];
    const float* b1  = (const float*)d_in[5];
    const float* W2  = (const float*)d_in[6];
    const float* b2  = (const float*)d_in[7];
    float* out = (float*)d_out;

    const int E  = in_sizes[1] / 2;
    const int Ep = in_sizes[2] / 2;
    const int En = in_sizes[3] / 2;
    const int Q  = Ep + En;

    float *hs1, *hs2, *z, *h;
    __nv_bfloat16 *w1thi, *w1tlo, *w2thi, *w2tlo;
    cudaGetSymbolAddress((void**)&hs1,   g_hs1);
    cudaGetSymbolAddress((void**)&hs2,   g_hs2);
    cudaGetSymbolAddress((void**)&z,     g_z);
    cudaGetSymbolAddress((void**)&h,     g_h);
    cudaGetSymbolAddress((void**)&w1thi, g_w1thi);
    cudaGetSymbolAddress((void**)&w1tlo, g_w1tlo);
    cudaGetSymbolAddress((void**)&w2thi, g_w2thi);
    cudaGetSymbolAddress((void**)&w2tlo, g_w2tlo);

    constexpr int SMEM1 = 2 * (2 * (128 * 128) + 2 * (C1 * 128));  // 131072
    constexpr int SMEM2 = 2 * (2 * (128 * 128) + 2 * (C2 * 128));  // 98304
    cudaFuncSetAttribute(mma_gemm_kernel<C1, CIN>, cudaFuncAttributeMaxDynamicSharedMemorySize, SMEM1);
    cudaFuncSetAttribute(mma_gemm_kernel<C2, C1>,  cudaFuncAttributeMaxDynamicSharedMemorySize, SMEM2);

    // side stream + fork/join events (created once, on the uncaptured correctness call)
    static cudaStream_t s2 = nullptr;
    static cudaEvent_t evFork = nullptr, evJoin = nullptr;
    if (!s2) {
        cudaStreamCreateWithFlags(&s2, cudaStreamNonBlocking);
        cudaEventCreateWithFlags(&evFork, cudaEventDisableTiming);
        cudaEventCreateWithFlags(&evJoin, cudaEventDisableTiming);
    }

    const int NTILES = NPAD / 128;        // 391
    const int EB = (E + 255) / 256;       // 3125
    const int QB = (Q + 255) / 256;       // 1563

    // main stream: prep -> GEMM1 ----------------------------> gather128 -> ...
    // side stream:        \-> converts -> scan -> fill  --/
    prep_kernel<<<PREP_BLOCKS, 256>>>(W1, W2, (const int*)ei);                          // launch 0
    cudaEventRecord(evFork, 0);
    cudaStreamWaitEvent(s2, evFork, 0);

    converts_kernel<<<EB + QB, 256, 0, s2>>>(ei, pos, neg, E, Ep, En, EB);              // launch 1
    scan_dinv_kernel<<<1, 1024, 0, s2>>>();                                              // launch 2
    mma_gemm_kernel<C1, CIN><<<NTILES, 256, SMEM1>>>(x, w1thi, w1tlo, hs1, N_NODES);    // launch 3 (profiled)
    fill_kernel<<<EB, 256, 0, s2>>>(E);                                                  // launch 4
    cudaEventRecord(evJoin, s2);
    cudaStreamWaitEvent(0, evJoin, 0);

    gather128_kernel<<<(N_NODES * 32 + 255) / 256, 256>>>(hs1, b1);                      // launch 5
    mma_gemm_kernel<C2, C1><<<NTILES, 256, SMEM2>>>(h, w2thi, w2tlo, hs2, N_NODES);     // launch 6
    gather64_kernel<<<(N_NODES * 32 + 255) / 256, 256>>>(hs2, z, b2);                    // launch 7
    {
        long long tot = (long long)Q * 16;
        logits_kernel<<<(int)((tot + 255) / 256), 256>>>(Q, z, out);                     // launch 8
    }
}